// round 11
// baseline (speedup 1.0000x reference)
#include <cuda_runtime.h>
#include <cuda_bf16.h>
#include <stdint.h>
#include <math.h>

// Problem constants (B=1)
#define SEQ   2048
#define HID   4096
#define NH    32
#define NKV   8
#define HD    128
#define QDIM  (NH * HD)   // 4096
#define KVDIM (NKV * HD)  // 1024
#define RSCALE 0.08838834764831845f  // 128^-0.5
#define REPS   1e-6f

// ---------------------------------------------------------------------------
// Scratch (__device__ globals: allocation-free rule)
// ---------------------------------------------------------------------------
__device__ float g_Q[SEQ * QDIM];
__device__ float g_K[SEQ * KVDIM];
__device__ float g_AO[SEQ * QDIM];

__device__ __nv_bfloat16 g_Qh2[SEQ * QDIM],   g_Ql2[SEQ * QDIM];
__device__ __nv_bfloat16 g_Kh2[SEQ * KVDIM],  g_Kl2[SEQ * KVDIM];
__device__ __nv_bfloat16 g_Vh2[SEQ * KVDIM],  g_Vl2[SEQ * KVDIM];

// ---------------------------------------------------------------------------
// PTX helpers (base sm_100-safe)
// ---------------------------------------------------------------------------
__device__ __forceinline__ uint32_t smem_u32(const void* p) {
    uint32_t a;
    asm("{ .reg .u64 t; cvta.to.shared.u64 t, %1; cvt.u32.u64 %0, t; }"
        : "=r"(a) : "l"(p));
    return a;
}

__device__ __forceinline__ void ldsm4(uint32_t* r, uint32_t addr) {
    asm volatile("ldmatrix.sync.aligned.m8n8.x4.shared.b16 {%0,%1,%2,%3}, [%4];"
                 : "=r"(r[0]), "=r"(r[1]), "=r"(r[2]), "=r"(r[3]) : "r"(addr));
}

__device__ __forceinline__ void ldsm4t(uint32_t* r, uint32_t addr) {
    asm volatile("ldmatrix.sync.aligned.m8n8.x4.trans.shared.b16 {%0,%1,%2,%3}, [%4];"
                 : "=r"(r[0]), "=r"(r[1]), "=r"(r[2]), "=r"(r[3]) : "r"(addr));
}

__device__ __forceinline__ void mma16816(float* c, const uint32_t* a,
                                         uint32_t b0, uint32_t b1) {
    asm volatile(
        "mma.sync.aligned.m16n8k16.row.col.f32.bf16.bf16.f32 "
        "{%0,%1,%2,%3}, {%4,%5,%6,%7}, {%8,%9}, {%0,%1,%2,%3};"
        : "+f"(c[0]), "+f"(c[1]), "+f"(c[2]), "+f"(c[3])
        : "r"(a[0]), "r"(a[1]), "r"(a[2]), "r"(a[3]), "r"(b0), "r"(b1));
}

__device__ __forceinline__ uint32_t pack_bf16(float lo, float hi) {
    __nv_bfloat162 t;
    t.x = __float2bfloat16(lo);
    t.y = __float2bfloat16(hi);
    return *(uint32_t*)&t;
}

__device__ __forceinline__ void split2(float a, float b,
                                       __nv_bfloat162* h, __nv_bfloat162* l) {
    __nv_bfloat16 ha = __float2bfloat16(a);
    __nv_bfloat16 hb = __float2bfloat16(b);
    h->x = ha; h->y = hb;
    l->x = __float2bfloat16(a - __bfloat162float(ha));
    l->y = __float2bfloat16(b - __bfloat162float(hb));
}

// ---------------------------------------------------------------------------
// mma.sync bf16x3 GEMM, fp32 inputs with in-kernel split conversion.
// 512 threads (16 warps, 4x4 grid of 32x32 warp tiles), 128x128 CTA tile,
// BK=64, LDG distance-1 prefetch into regs -> split2 -> STS bf16 tiles,
// 2 smem buffers (64KB each).
// ---------------------------------------------------------------------------
#define GTHREADS 512
#define TILE_B   16384                  // one bf16 tile: 128 rows x 128B
#define BUF_B    (4 * TILE_B)           // Ahi,Alo,Bhi,Blo
#define GSM_TOTAL (2 * BUF_B)           // 131072

__device__ __forceinline__ void ldg_chunk(
    const float* __restrict__ A, const float* __restrict__ B,
    int K, int bm, int bn, int kc, int tid, float4* stg)
{
#pragma unroll
    for (int s = 0; s < 2; s++) {
        int idx = tid + s * GTHREADS;    // 0..1023
        int r = idx >> 3;                // 0..127
        int j = idx & 7;                 // 16B-unit (8 bf16 cols)
        const float4* pa = (const float4*)(A + (size_t)(bm + r) * K + kc * 64 + j * 8);
        stg[2 * s]     = pa[0];
        stg[2 * s + 1] = pa[1];
        const float4* pb = (const float4*)(B + (size_t)(bn + r) * K + kc * 64 + j * 8);
        stg[4 + 2 * s]     = pb[0];
        stg[4 + 2 * s + 1] = pb[1];
    }
}

__device__ __forceinline__ void sts_pair(uint32_t hi_addr, uint32_t lo_addr,
                                         float4 v0, float4 v1)
{
    __nv_bfloat162 h0, l0, h1, l1, h2, l2, h3, l3;
    split2(v0.x, v0.y, &h0, &l0);
    split2(v0.z, v0.w, &h1, &l1);
    split2(v1.x, v1.y, &h2, &l2);
    split2(v1.z, v1.w, &h3, &l3);
    asm volatile("st.shared.v4.b32 [%0], {%1,%2,%3,%4};"
                 :: "r"(hi_addr), "r"(*(uint32_t*)&h0), "r"(*(uint32_t*)&h1),
                    "r"(*(uint32_t*)&h2), "r"(*(uint32_t*)&h3) : "memory");
    asm volatile("st.shared.v4.b32 [%0], {%1,%2,%3,%4};"
                 :: "r"(lo_addr), "r"(*(uint32_t*)&l0), "r"(*(uint32_t*)&l1),
                    "r"(*(uint32_t*)&l2), "r"(*(uint32_t*)&l3) : "memory");
}

__device__ __forceinline__ void sts_chunk(uint32_t buf, int tid, const float4* stg)
{
#pragma unroll
    for (int s = 0; s < 2; s++) {
        int idx = tid + s * GTHREADS;
        int r = idx >> 3;
        int j = idx & 7;
        uint32_t sw = (uint32_t)(r * 128 + ((j ^ (r & 7)) << 4));
        sts_pair(buf + sw,              buf + TILE_B + sw,
                 stg[2 * s], stg[2 * s + 1]);
        sts_pair(buf + 2 * TILE_B + sw, buf + 3 * TILE_B + sw,
                 stg[4 + 2 * s], stg[4 + 2 * s + 1]);
    }
}

__device__ __forceinline__ void gemm_core(
    const float* __restrict__ A, const float* __restrict__ B,
    float* __restrict__ C,
    __nv_bfloat16* __restrict__ Chi, __nv_bfloat16* __restrict__ Clo,
    int N, int K, int bm, int bn, char* smem)
{
    const uint32_t sb = smem_u32(smem);
    const int tid  = threadIdx.x;
    const int lane = tid & 31;
    const int warp = tid >> 5;
    const int wm = warp >> 2;     // 0..3 -> row offset wm*32
    const int wn = warp & 3;      // 0..3 -> col offset wn*32
    const int NC = K >> 6;

    float acc[2][4][4];
#pragma unroll
    for (int i = 0; i < 2; i++)
#pragma unroll
        for (int j = 0; j < 4; j++)
#pragma unroll
            for (int q = 0; q < 4; q++) acc[i][j][q] = 0.0f;

    float4 stg[8];
    ldg_chunk(A, B, K, bm, bn, 0, tid, stg);

    const int a_r  = wm * 32 + (lane & 15);
    const int a_ku = lane >> 4;
    const int b_r  = wn * 32 + ((lane >> 3) & 1) * 8 + (lane & 7);
    const int b_ku = lane >> 4;

    for (int c = 0; c < NC; c++) {
        __syncthreads();   // all warps done computing chunk c-1; buf[c&1] free
        const uint32_t buf = sb + (c & 1) * BUF_B;
        sts_chunk(buf, tid, stg);
        if (c + 1 < NC) ldg_chunk(A, B, K, bm, bn, c + 1, tid, stg);
        __syncthreads();   // buf[c&1] (chunk c) visible to all warps

        const uint32_t sAh = buf;
        const uint32_t sAl = buf + TILE_B;
        const uint32_t sBh = buf + 2 * TILE_B;
        const uint32_t sBl = buf + 3 * TILE_B;

#pragma unroll
        for (int ks = 0; ks < 4; ks++) {
            const int ku0 = ks * 2;
            uint32_t aH[2][4], aL[2][4];
#pragma unroll
            for (int mt = 0; mt < 2; mt++) {
                int r = a_r + mt * 16;
                int ku = ku0 + a_ku;
                uint32_t off = (uint32_t)(r * 128 + ((ku ^ (r & 7)) << 4));
                ldsm4(aH[mt], sAh + off);
                ldsm4(aL[mt], sAl + off);
            }
            uint32_t bH[2][4], bL[2][4];
#pragma unroll
            for (int ntp = 0; ntp < 2; ntp++) {
                int r = b_r + ntp * 16;
                int ku = ku0 + b_ku;
                uint32_t off = (uint32_t)(r * 128 + ((ku ^ (r & 7)) << 4));
                ldsm4(bH[ntp], sBh + off);
                ldsm4(bL[ntp], sBl + off);
            }
#pragma unroll
            for (int mt = 0; mt < 2; mt++) {
#pragma unroll
                for (int nt = 0; nt < 4; nt++) {
                    const int ntp = nt >> 1;
                    const int sel = nt & 1;
                    mma16816(acc[mt][nt], aH[mt], bH[ntp][sel], bH[ntp][sel + 2]);
                    mma16816(acc[mt][nt], aH[mt], bL[ntp][sel], bL[ntp][sel + 2]);
                    mma16816(acc[mt][nt], aL[mt], bH[ntp][sel], bH[ntp][sel + 2]);
                }
            }
        }
    }

    // Epilogue
#pragma unroll
    for (int mt = 0; mt < 2; mt++) {
        const int row = bm + wm * 32 + mt * 16 + (lane >> 2);
#pragma unroll
        for (int nt = 0; nt < 4; nt++) {
            const int col = bn + wn * 32 + nt * 8 + (lane & 3) * 2;
            if (C) {
                *(float2*)(C + (size_t)row * N + col) =
                    make_float2(acc[mt][nt][0], acc[mt][nt][1]);
                *(float2*)(C + (size_t)(row + 8) * N + col) =
                    make_float2(acc[mt][nt][2], acc[mt][nt][3]);
            } else {
                __nv_bfloat162 h, l;
                split2(acc[mt][nt][0], acc[mt][nt][1], &h, &l);
                *(__nv_bfloat162*)(Chi + (size_t)row * N + col) = h;
                *(__nv_bfloat162*)(Clo + (size_t)row * N + col) = l;
                split2(acc[mt][nt][2], acc[mt][nt][3], &h, &l);
                *(__nv_bfloat162*)(Chi + (size_t)(row + 8) * N + col) = h;
                *(__nv_bfloat162*)(Clo + (size_t)(row + 8) * N + col) = l;
            }
        }
    }
}

// Plain GEMM kernel (Q-proj / O-proj), fp32 in, fp32 out
__global__ __launch_bounds__(GTHREADS)
void gemm_f32(const float* __restrict__ A, const float* __restrict__ B,
              float* __restrict__ C, int N, int K)
{
    extern __shared__ __align__(1024) char smem[];
    gemm_core(A, B, C, nullptr, nullptr, N, K,
              blockIdx.y * 128, blockIdx.x * 128, smem);
}

// Fused K+V projection: blockIdx.x < 8 -> K (fp32 out), else V (split out)
__global__ __launch_bounds__(GTHREADS)
void gemm_kv(const float* __restrict__ X,
             const float* __restrict__ Wk, const float* __restrict__ Wv,
             float* __restrict__ Ck,
             __nv_bfloat16* __restrict__ Cvh, __nv_bfloat16* __restrict__ Cvl)
{
    extern __shared__ __align__(1024) char smem[];
    const int bx = blockIdx.x;
    if (bx < KVDIM / 128) {
        gemm_core(X, Wk, Ck, nullptr, nullptr, KVDIM, HID,
                  blockIdx.y * 128, bx * 128, smem);
    } else {
        gemm_core(X, Wv, nullptr, Cvh, Cvl, KVDIM, HID,
                  blockIdx.y * 128, (bx - KVDIM / 128) * 128, smem);
    }
}

// ---------------------------------------------------------------------------
// Fused RMSNorm + RoPE for BOTH Q and K in one launch, bf16 hi/lo out.
// ---------------------------------------------------------------------------
#define RMS_BLOCKS (8192 + 2048)

__global__ __launch_bounds__(256) void rms_both(
    const float* __restrict__ Qf, const float* __restrict__ Kf,
    const float* __restrict__ qw, const float* __restrict__ kw,
    const float* __restrict__ cosb, const float* __restrict__ sinb,
    __nv_bfloat16* __restrict__ qh, __nv_bfloat16* __restrict__ ql,
    __nv_bfloat16* __restrict__ kh, __nv_bfloat16* __restrict__ kl)
{
    const int b = blockIdx.x;
    const float* X;
    const float* w;
    __nv_bfloat16 *oh, *ol;
    int nheads, row;
    if (b < 8192) { X = Qf; w = qw; oh = qh; ol = ql; nheads = NH;  row = b * 8; }
    else          { X = Kf; w = kw; oh = kh; ol = kl; nheads = NKV; row = (b - 8192) * 8; }
    row += threadIdx.x >> 5;
    const int lane = threadIdx.x & 31;
    const int s = row / nheads;

    const float* x = X + (size_t)row * HD;
    float4 v = *(const float4*)(x + lane * 4);

    float ss = v.x * v.x + v.y * v.y + v.z * v.z + v.w * v.w;
#pragma unroll
    for (int o = 16; o > 0; o >>= 1) ss += __shfl_xor_sync(0xffffffffu, ss, o);
    const float inv = rsqrtf(ss * (1.0f / 128.0f) + REPS);

    float4 wv = *(const float4*)(w + lane * 4);
    float x0 = v.x * inv * wv.x;
    float x1 = v.y * inv * wv.y;
    float x2 = v.z * inv * wv.z;
    float x3 = v.w * inv * wv.w;

    float p0 = __shfl_xor_sync(0xffffffffu, x0, 16);
    float p1 = __shfl_xor_sync(0xffffffffu, x1, 16);
    float p2 = __shfl_xor_sync(0xffffffffu, x2, 16);
    float p3 = __shfl_xor_sync(0xffffffffu, x3, 16);
    const float sgn = (lane < 16) ? -1.0f : 1.0f;

    const float* cp = cosb + (size_t)s * HD + lane * 4;
    const float* sp = sinb + (size_t)s * HD + lane * 4;
    float4 c = *(const float4*)cp;
    float4 sn = *(const float4*)sp;

    float o0 = x0 * c.x + sgn * p0 * sn.x;
    float o1 = x1 * c.y + sgn * p1 * sn.y;
    float o2 = x2 * c.z + sgn * p2 * sn.z;
    float o3 = x3 * c.w + sgn * p3 * sn.w;

    __nv_bfloat162 h, l;
    size_t base = (size_t)row * HD + lane * 4;
    split2(o0, o1, &h, &l);
    *(__nv_bfloat162*)(oh + base)     = h;
    *(__nv_bfloat162*)(ol + base)     = l;
    split2(o2, o3, &h, &l);
    *(__nv_bfloat162*)(oh + base + 2) = h;
    *(__nv_bfloat162*)(ol + base + 2) = l;
}

// ---------------------------------------------------------------------------
// Tensor-core flash attention (bf16 split), causal, GQA, 3-stage pipeline,
// single sync per KV block. Writes fp32 AO.
// ---------------------------------------------------------------------------
#define KVTILE_B 16384                    // 64 rows x 256B
#define ASTAGE_B (4 * KVTILE_B)           // Kh,Kl,Vh,Vl
#define ASM_TOTAL (3 * ASTAGE_B)          // 196608

__device__ __forceinline__ uint32_t swz256(int r, int u) {
    return (uint32_t)(r * 256 + ((u ^ (r & 7)) << 4));
}

__device__ __forceinline__ void attn_load_kv(
    uint32_t base, const __nv_bfloat16* __restrict__ Kh,
    const __nv_bfloat16* __restrict__ Kl, const __nv_bfloat16* __restrict__ Vh,
    const __nv_bfloat16* __restrict__ Vl, int k0, int kvh, int tid)
{
#pragma unroll
    for (int t = 0; t < 4; t++) {
        int idx = tid + t * 256;
        int r = idx >> 4, u = idx & 15;
        size_t go = (size_t)(k0 + r) * KVDIM + kvh * HD + u * 8;
        uint32_t sw = swz256(r, u);
        asm volatile("cp.async.cg.shared.global [%0], [%1], 16;"
                     :: "r"(base + sw), "l"(Kh + go) : "memory");
        asm volatile("cp.async.cg.shared.global [%0], [%1], 16;"
                     :: "r"(base + KVTILE_B + sw), "l"(Kl + go) : "memory");
        asm volatile("cp.async.cg.shared.global [%0], [%1], 16;"
                     :: "r"(base + 2 * KVTILE_B + sw), "l"(Vh + go) : "memory");
        asm volatile("cp.async.cg.shared.global [%0], [%1], 16;"
                     :: "r"(base + 3 * KVTILE_B + sw), "l"(Vl + go) : "memory");
    }
}

__global__ __launch_bounds__(256, 1)
void attn_mma(const __nv_bfloat16* __restrict__ Qh, const __nv_bfloat16* __restrict__ Ql,
              const __nv_bfloat16* __restrict__ Kh, const __nv_bfloat16* __restrict__ Kl,
              const __nv_bfloat16* __restrict__ Vh, const __nv_bfloat16* __restrict__ Vl,
              float* __restrict__ O)
{
    extern __shared__ __align__(1024) char smem[];
    const uint32_t sb = smem_u32(smem);
    const int tid  = threadIdx.x;
    const int lane = tid & 31;
    const int warp = tid >> 5;
    const int qb = (int)gridDim.x - 1 - (int)blockIdx.x;
    const int h  = blockIdx.y;
    const int kvh = h >> 2;
    const int q0 = qb * 128;
    const int NB = 2 * qb + 2;

    // ---- Stage Q through smem, build register fragments (hi then lo)
    uint32_t qfh[8][4], qfl[8][4];
#pragma unroll
    for (int comp = 0; comp < 2; comp++) {
        const __nv_bfloat16* src = comp ? Ql : Qh;
        for (int t = 0; t < 8; t++) {
            int idx = tid + t * 256;
            int r = idx >> 4, u = idx & 15;
            const __nv_bfloat16* gp = src + (size_t)(q0 + r) * QDIM + h * HD + u * 8;
            asm volatile("cp.async.cg.shared.global [%0], [%1], 16;"
                         :: "r"(sb + swz256(r, u)), "l"(gp) : "memory");
        }
        asm volatile("cp.async.commit_group;" ::: "memory");
        asm volatile("cp.async.wait_group 0;" ::: "memory");
        __syncthreads();
        {
            int r = warp * 16 + (lane & 15);
#pragma unroll
            for (int ks = 0; ks < 8; ks++) {
                uint32_t addr = sb + swz256(r, 2 * ks + (lane >> 4));
                if (comp) ldsm4(qfl[ks], addr);
                else      ldsm4(qfh[ks], addr);
            }
        }
        __syncthreads();
    }

    float o[16][4];
#pragma unroll
    for (int i = 0; i < 16; i++)
#pragma unroll
        for (int q = 0; q < 4; q++) o[i][q] = 0.0f;
    float m0 = -1e30f, m1 = -1e30f, l0 = 0.0f, l1 = 0.0f;

    const int row0 = q0 + warp * 16 + (lane >> 2);
    const int row1 = row0 + 8;

    // ---- prologue: stages 0 and 1
    attn_load_kv(sb, Kh, Kl, Vh, Vl, 0, kvh, tid);
    asm volatile("cp.async.commit_group;" ::: "memory");
    if (NB > 1) {
        attn_load_kv(sb + ASTAGE_B, Kh, Kl, Vh, Vl, 64, kvh, tid);
        asm volatile("cp.async.commit_group;" ::: "memory");
    }

    int buf = 0;
    for (int kb = 0; kb < NB; kb++) {
        if (kb + 1 < NB)
            asm volatile("cp.async.wait_group 1;" ::: "memory");
        else
            asm volatile("cp.async.wait_group 0;" ::: "memory");
        __syncthreads();   // block kb visible AND all warps done with block kb-1

        if (kb + 2 < NB) {
            int nb = buf + 2; if (nb >= 3) nb -= 3;
            attn_load_kv(sb + nb * ASTAGE_B, Kh, Kl, Vh, Vl, (kb + 2) * 64, kvh, tid);
            asm volatile("cp.async.commit_group;" ::: "memory");
        }

        const uint32_t bK = sb + buf * ASTAGE_B;
        const int k0 = kb * 64;

        // ---- S = Q K^T (bf16x3)
        float s[8][4];
#pragma unroll
        for (int nt = 0; nt < 8; nt++)
#pragma unroll
            for (int q = 0; q < 4; q++) s[nt][q] = 0.0f;

#pragma unroll
        for (int ks = 0; ks < 8; ks++) {
#pragma unroll
            for (int g = 0; g < 4; g++) {
                uint32_t kh4[4], kl4[4];
                int rr = g * 16 + ((lane >> 3) & 1) * 8 + (lane & 7);
                uint32_t off = swz256(rr, 2 * ks + (lane >> 4));
                ldsm4(kh4, bK + off);
                ldsm4(kl4, bK + KVTILE_B + off);
#pragma unroll
                for (int sel = 0; sel < 2; sel++) {
                    int nt = g * 2 + sel;
                    mma16816(s[nt], qfh[ks], kh4[sel], kh4[sel + 2]);
                    mma16816(s[nt], qfh[ks], kl4[sel], kl4[sel + 2]);
                    mma16816(s[nt], qfl[ks], kh4[sel], kh4[sel + 2]);
                }
            }
        }

        // ---- scale + causal mask
        const bool domask = (k0 + 63) > row0;
#pragma unroll
        for (int nt = 0; nt < 8; nt++) {
            int c0 = k0 + nt * 8 + (lane & 3) * 2;
#pragma unroll
            for (int q = 0; q < 4; q++) s[nt][q] *= RSCALE;
            if (domask) {
                if (c0     > row0) s[nt][0] = -1e30f;
                if (c0 + 1 > row0) s[nt][1] = -1e30f;
                if (c0     > row1) s[nt][2] = -1e30f;
                if (c0 + 1 > row1) s[nt][3] = -1e30f;
            }
        }

        // ---- online softmax
        float mx0 = -1e30f, mx1 = -1e30f;
#pragma unroll
        for (int nt = 0; nt < 8; nt++) {
            mx0 = fmaxf(mx0, fmaxf(s[nt][0], s[nt][1]));
            mx1 = fmaxf(mx1, fmaxf(s[nt][2], s[nt][3]));
        }
        mx0 = fmaxf(mx0, __shfl_xor_sync(0xffffffffu, mx0, 1));
        mx0 = fmaxf(mx0, __shfl_xor_sync(0xffffffffu, mx0, 2));
        mx1 = fmaxf(mx1, __shfl_xor_sync(0xffffffffu, mx1, 1));
        mx1 = fmaxf(mx1, __shfl_xor_sync(0xffffffffu, mx1, 2));

        float mn0 = fmaxf(m0, mx0), mn1 = fmaxf(m1, mx1);
        float a0 = __expf(m0 - mn0), a1 = __expf(m1 - mn1);
        m0 = mn0; m1 = mn1;

        float sum0 = 0.0f, sum1 = 0.0f;
#pragma unroll
        for (int nt = 0; nt < 8; nt++) {
            s[nt][0] = __expf(s[nt][0] - mn0);
            s[nt][1] = __expf(s[nt][1] - mn0);
            s[nt][2] = __expf(s[nt][2] - mn1);
            s[nt][3] = __expf(s[nt][3] - mn1);
            sum0 += s[nt][0] + s[nt][1];
            sum1 += s[nt][2] + s[nt][3];
        }
        sum0 += __shfl_xor_sync(0xffffffffu, sum0, 1);
        sum0 += __shfl_xor_sync(0xffffffffu, sum0, 2);
        sum1 += __shfl_xor_sync(0xffffffffu, sum1, 1);
        sum1 += __shfl_xor_sync(0xffffffffu, sum1, 2);
        l0 = l0 * a0 + sum0;
        l1 = l1 * a1 + sum1;

#pragma unroll
        for (int nt = 0; nt < 16; nt++) {
            o[nt][0] *= a0; o[nt][1] *= a0;
            o[nt][2] *= a1; o[nt][3] *= a1;
        }

        // ---- O += P V (bf16 split P and V)
#pragma unroll
        for (int kt = 0; kt < 4; kt++) {
            uint32_t pah[4], pal[4];
            {
                float e[8] = { s[2*kt][0], s[2*kt][1], s[2*kt][2], s[2*kt][3],
                               s[2*kt+1][0], s[2*kt+1][1], s[2*kt+1][2], s[2*kt+1][3] };
                float hf[8], lf[8];
#pragma unroll
                for (int q = 0; q < 8; q++) {
                    __nv_bfloat16 hb = __float2bfloat16(e[q]);
                    hf[q] = __bfloat162float(hb);
                    lf[q] = e[q] - hf[q];
                }
                pah[0] = pack_bf16(hf[0], hf[1]);
                pah[1] = pack_bf16(hf[2], hf[3]);
                pah[2] = pack_bf16(hf[4], hf[5]);
                pah[3] = pack_bf16(hf[6], hf[7]);
                pal[0] = pack_bf16(lf[0], lf[1]);
                pal[1] = pack_bf16(lf[2], lf[3]);
                pal[2] = pack_bf16(lf[4], lf[5]);
                pal[3] = pack_bf16(lf[6], lf[7]);
            }
            const int j = lane >> 3, ll = lane & 7;
            const int rr = kt * 16 + (j & 1) * 8 + ll;
#pragma unroll
            for (int gn = 0; gn < 8; gn++) {
                uint32_t vh4[4], vl4[4];
                uint32_t off = swz256(rr, gn * 2 + (j >> 1));
                ldsm4t(vh4, bK + 2 * KVTILE_B + off);
                ldsm4t(vl4, bK + 3 * KVTILE_B + off);
#pragma unroll
                for (int sel = 0; sel < 2; sel++) {
                    int nt = gn * 2 + sel;
                    mma16816(o[nt], pah, vh4[sel * 2], vh4[sel * 2 + 1]);
                    mma16816(o[nt], pah, vl4[sel * 2], vl4[sel * 2 + 1]);
                    mma16816(o[nt], pal, vh4[sel * 2], vh4[sel * 2 + 1]);
                }
            }
        }
        if (++buf == 3) buf = 0;
    }

    // ---- finalize: write fp32 AO
    const float i0 = 1.0f / l0, i1 = 1.0f / l1;
#pragma unroll
    for (int nt = 0; nt < 16; nt++) {
        int col = h * HD + nt * 8 + (lane & 3) * 2;
        *(float2*)(O + (size_t)row0 * QDIM + col) =
            make_float2(o[nt][0] * i0, o[nt][1] * i0);
        *(float2*)(O + (size_t)row1 * QDIM + col) =
            make_float2(o[nt][2] * i1, o[nt][3] * i1);
    }
}

// ---------------------------------------------------------------------------
extern "C" void kernel_launch(void* const* d_in, const int* in_sizes, int n_in,
                              void* d_out, int out_size)
{
    const float* hidden = (const float*)d_in[0];
    const float* cosb   = (const float*)d_in[1];
    const float* sinb   = (const float*)d_in[2];
    const float* Wq     = (const float*)d_in[3];
    const float* Wk     = (const float*)d_in[4];
    const float* Wv     = (const float*)d_in[5];
    const float* Wo     = (const float*)d_in[6];
    const float* qw     = (const float*)d_in[7];
    const float* kw     = (const float*)d_in[8];
    float* out = (float*)d_out;

    float *Qp, *Kp, *AOp;
    cudaGetSymbolAddress((void**)&Qp,  g_Q);
    cudaGetSymbolAddress((void**)&Kp,  g_K);
    cudaGetSymbolAddress((void**)&AOp, g_AO);

    __nv_bfloat16 *Qh2, *Ql2, *Kh2, *Kl2, *Vh2, *Vl2;
    cudaGetSymbolAddress((void**)&Qh2, g_Qh2);  cudaGetSymbolAddress((void**)&Ql2, g_Ql2);
    cudaGetSymbolAddress((void**)&Kh2, g_Kh2);  cudaGetSymbolAddress((void**)&Kl2, g_Kl2);
    cudaGetSymbolAddress((void**)&Vh2, g_Vh2);  cudaGetSymbolAddress((void**)&Vl2, g_Vl2);

    cudaFuncSetAttribute(gemm_f32,
                         cudaFuncAttributeMaxDynamicSharedMemorySize, GSM_TOTAL);
    cudaFuncSetAttribute(gemm_kv,
                         cudaFuncAttributeMaxDynamicSharedMemorySize, GSM_TOTAL);
    cudaFuncSetAttribute(attn_mma,
                         cudaFuncAttributeMaxDynamicSharedMemorySize, ASM_TOTAL);

    // L0: Q projection (fp32 in, fp32 out, in-kernel split)
    gemm_f32<<<dim3(QDIM / 128, SEQ / 128), GTHREADS, GSM_TOTAL>>>(
        hidden, Wq, Qp, QDIM, HID);

    // L1: fused K+V projection
    gemm_kv<<<dim3(2 * KVDIM / 128, SEQ / 128), GTHREADS, GSM_TOTAL>>>(
        hidden, Wk, Wv, Kp, Vh2, Vl2);

    // L2: RMSNorm + RoPE for Q and K in one launch -> bf16 hi/lo
    rms_both<<<RMS_BLOCKS, 256>>>(Qp, Kp, qw, kw, cosb, sinb,
                                  Qh2, Ql2, Kh2, Kl2);

    // L3: tensor-core flash attention -> fp32 AO
    attn_mma<<<dim3(SEQ / 128, NH), 256, ASM_TOTAL>>>(
        Qh2, Ql2, Kh2, Kl2, Vh2, Vl2, AOp);

    // L4: output projection
    gemm_f32<<<dim3(HID / 128, SEQ / 128), GTHREADS, GSM_TOTAL>>>(
        AOp, Wo, out, HID, QDIM);
}

// round 12
// speedup vs baseline: 1.1517x; 1.1517x over previous
#include <cuda_runtime.h>
#include <cuda_bf16.h>
#include <stdint.h>
#include <math.h>

// Problem constants (B=1)
#define SEQ   2048
#define HID   4096
#define NH    32
#define NKV   8
#define HD    128
#define QDIM  (NH * HD)   // 4096
#define KVDIM (NKV * HD)  // 1024
#define RSCALE 0.08838834764831845f  // 128^-0.5
#define REPS   1e-6f

// ---------------------------------------------------------------------------
// Scratch (__device__ globals: allocation-free rule)
// ---------------------------------------------------------------------------
__device__ float g_Q[SEQ * QDIM];
__device__ float g_K[SEQ * KVDIM];

__device__ __nv_bfloat16 g_Xhi[SEQ * HID],    g_Xlo[SEQ * HID];
__device__ __nv_bfloat16 g_Wqh[QDIM * HID],   g_Wql[QDIM * HID];
__device__ __nv_bfloat16 g_Wkh[KVDIM * HID],  g_Wkl[KVDIM * HID];
__device__ __nv_bfloat16 g_Wvh[KVDIM * HID],  g_Wvl[KVDIM * HID];
__device__ __nv_bfloat16 g_Woh[HID * QDIM],   g_Wol[HID * QDIM];
__device__ __nv_bfloat16 g_AOh[SEQ * QDIM],   g_AOl[SEQ * QDIM];

__device__ __nv_bfloat16 g_Qh2[SEQ * QDIM],   g_Ql2[SEQ * QDIM];
__device__ __nv_bfloat16 g_Kh2[SEQ * KVDIM],  g_Kl2[SEQ * KVDIM];
__device__ __nv_bfloat16 g_Vh2[SEQ * KVDIM],  g_Vl2[SEQ * KVDIM];

// ---------------------------------------------------------------------------
// PTX helpers (base sm_100-safe)
// ---------------------------------------------------------------------------
__device__ __forceinline__ uint32_t smem_u32(const void* p) {
    uint32_t a;
    asm("{ .reg .u64 t; cvta.to.shared.u64 t, %1; cvt.u32.u64 %0, t; }"
        : "=r"(a) : "l"(p));
    return a;
}

__device__ __forceinline__ void ldsm4(uint32_t* r, uint32_t addr) {
    asm volatile("ldmatrix.sync.aligned.m8n8.x4.shared.b16 {%0,%1,%2,%3}, [%4];"
                 : "=r"(r[0]), "=r"(r[1]), "=r"(r[2]), "=r"(r[3]) : "r"(addr));
}

__device__ __forceinline__ void ldsm4t(uint32_t* r, uint32_t addr) {
    asm volatile("ldmatrix.sync.aligned.m8n8.x4.trans.shared.b16 {%0,%1,%2,%3}, [%4];"
                 : "=r"(r[0]), "=r"(r[1]), "=r"(r[2]), "=r"(r[3]) : "r"(addr));
}

__device__ __forceinline__ void mma16816(float* c, const uint32_t* a,
                                         uint32_t b0, uint32_t b1) {
    asm volatile(
        "mma.sync.aligned.m16n8k16.row.col.f32.bf16.bf16.f32 "
        "{%0,%1,%2,%3}, {%4,%5,%6,%7}, {%8,%9}, {%0,%1,%2,%3};"
        : "+f"(c[0]), "+f"(c[1]), "+f"(c[2]), "+f"(c[3])
        : "r"(a[0]), "r"(a[1]), "r"(a[2]), "r"(a[3]), "r"(b0), "r"(b1));
}

__device__ __forceinline__ uint32_t pack_bf16(float lo, float hi) {
    __nv_bfloat162 t;
    t.x = __float2bfloat16(lo);
    t.y = __float2bfloat16(hi);
    return *(uint32_t*)&t;
}

__device__ __forceinline__ void split2(float a, float b,
                                       __nv_bfloat162* h, __nv_bfloat162* l) {
    __nv_bfloat16 ha = __float2bfloat16(a);
    __nv_bfloat16 hb = __float2bfloat16(b);
    h->x = ha; h->y = hb;
    l->x = __float2bfloat16(a - __bfloat162float(ha));
    l->y = __float2bfloat16(b - __bfloat162float(hb));
}

// ---------------------------------------------------------------------------
// Fused fp32 -> (bf16 hi, bf16 lo) split for X + Wq + Wk + Wv.
// (Wo conversion is folded into the Q-projection launch.)
//   X:  [0, 8192)   Wq: [8192, 24576)  Wk: [24576, 28672)  Wv: [28672, 32768)
// ---------------------------------------------------------------------------
#define CVT_BLOCKS 32768

__global__ __launch_bounds__(256) void cvt_all(
    const float* __restrict__ x,  __nv_bfloat16* __restrict__ xh,  __nv_bfloat16* __restrict__ xl,
    const float* __restrict__ wq, __nv_bfloat16* __restrict__ wqh, __nv_bfloat16* __restrict__ wql,
    const float* __restrict__ wk, __nv_bfloat16* __restrict__ wkh, __nv_bfloat16* __restrict__ wkl,
    const float* __restrict__ wv, __nv_bfloat16* __restrict__ wvh, __nv_bfloat16* __restrict__ wvl)
{
    const int b = blockIdx.x;
    const float* src;
    __nv_bfloat16 *hi, *lo;
    int base;
    if (b < 8192)       { src = x;  hi = xh;  lo = xl;  base = 0; }
    else if (b < 24576) { src = wq; hi = wqh; lo = wql; base = 8192; }
    else if (b < 28672) { src = wk; hi = wkh; lo = wkl; base = 24576; }
    else                { src = wv; hi = wvh; lo = wvl; base = 28672; }

    const int i = ((b - base) * 256 + threadIdx.x) * 4;
    float4 v = *(const float4*)(src + i);
    __nv_bfloat162 h0, l0, h1, l1;
    split2(v.x, v.y, &h0, &l0);
    split2(v.z, v.w, &h1, &l1);
    *(__nv_bfloat162*)(hi + i)     = h0;
    *(__nv_bfloat162*)(hi + i + 2) = h1;
    *(__nv_bfloat162*)(lo + i)     = l0;
    *(__nv_bfloat162*)(lo + i + 2) = l1;
}

// ---------------------------------------------------------------------------
// mma.sync bf16x3 GEMM core, 512 threads (16 warps, 4x4 grid of 32x32 warp
// tiles), 128x128 CTA tile, BK=64, 3-stage cp.async pipeline.
// ---------------------------------------------------------------------------
#define GTHREADS 512
#define TILE_B   16384
#define STAGE_B  (4 * TILE_B)
#define GSM_TOTAL (3 * STAGE_B)          // 196608

__device__ __forceinline__ void load_tile64(
    uint32_t sdst, const __nv_bfloat16* __restrict__ g,
    int row0, int kc, int K, int tid)
{
#pragma unroll
    for (int s = 0; s < 2; s++) {
        int idx = tid + s * GTHREADS;
        int r = idx >> 3;
        int u = idx & 7;
        uint32_t sw = (uint32_t)(r * 128 + ((u ^ (r & 7)) << 4));
        const __nv_bfloat16* gp = g + (size_t)(row0 + r) * K + kc * 64 + u * 8;
        asm volatile("cp.async.cg.shared.global [%0], [%1], 16;"
                     :: "r"(sdst + sw), "l"(gp) : "memory");
    }
}

__device__ __forceinline__ void gemm_core(
    const __nv_bfloat16* __restrict__ Ahi, const __nv_bfloat16* __restrict__ Alo,
    const __nv_bfloat16* __restrict__ Bhi, const __nv_bfloat16* __restrict__ Blo,
    float* __restrict__ C,
    __nv_bfloat16* __restrict__ Chi, __nv_bfloat16* __restrict__ Clo,
    int N, int K, int bm, int bn, char* smem)
{
    const uint32_t sb = smem_u32(smem);
    const int tid  = threadIdx.x;
    const int lane = tid & 31;
    const int warp = tid >> 5;
    const int wm = warp >> 2;     // 0..3 -> row offset wm*32
    const int wn = warp & 3;      // 0..3 -> col offset wn*32
    const int NC = K >> 6;

    float acc[2][4][4];
#pragma unroll
    for (int i = 0; i < 2; i++)
#pragma unroll
        for (int j = 0; j < 4; j++)
#pragma unroll
            for (int q = 0; q < 4; q++) acc[i][j][q] = 0.0f;

    // Prologue: stages 0 and 1
#pragma unroll
    for (int c = 0; c < 2; c++) {
        uint32_t b = sb + c * STAGE_B;
        load_tile64(b,              Ahi, bm, c, K, tid);
        load_tile64(b + TILE_B,     Alo, bm, c, K, tid);
        load_tile64(b + 2 * TILE_B, Bhi, bn, c, K, tid);
        load_tile64(b + 3 * TILE_B, Blo, bn, c, K, tid);
        asm volatile("cp.async.commit_group;" ::: "memory");
    }

    const int a_r  = wm * 32 + (lane & 15);
    const int a_ku = lane >> 4;
    const int b_r  = wn * 32 + ((lane >> 3) & 1) * 8 + (lane & 7);
    const int b_ku = lane >> 4;

    int buf = 0;
    for (int c = 0; c < NC; c++) {
        if (c + 1 < NC)
            asm volatile("cp.async.wait_group 1;" ::: "memory");
        else
            asm volatile("cp.async.wait_group 0;" ::: "memory");
        __syncthreads();   // chunk c visible AND all warps done with chunk c-1

        if (c + 2 < NC) {
            int nb = buf + 2; if (nb >= 3) nb -= 3;
            uint32_t b2 = sb + nb * STAGE_B;
            load_tile64(b2,              Ahi, bm, c + 2, K, tid);
            load_tile64(b2 + TILE_B,     Alo, bm, c + 2, K, tid);
            load_tile64(b2 + 2 * TILE_B, Bhi, bn, c + 2, K, tid);
            load_tile64(b2 + 3 * TILE_B, Blo, bn, c + 2, K, tid);
            asm volatile("cp.async.commit_group;" ::: "memory");
        }

        const uint32_t b = sb + buf * STAGE_B;
        const uint32_t sAh = b;
        const uint32_t sAl = b + TILE_B;
        const uint32_t sBh = b + 2 * TILE_B;
        const uint32_t sBl = b + 3 * TILE_B;

#pragma unroll
        for (int ks = 0; ks < 4; ks++) {
            const int ku0 = ks * 2;
            uint32_t aH[2][4], aL[2][4];
#pragma unroll
            for (int mt = 0; mt < 2; mt++) {
                int r = a_r + mt * 16;
                int ku = ku0 + a_ku;
                uint32_t off = (uint32_t)(r * 128 + ((ku ^ (r & 7)) << 4));
                ldsm4(aH[mt], sAh + off);
                ldsm4(aL[mt], sAl + off);
            }
            uint32_t bH[2][4], bL[2][4];
#pragma unroll
            for (int ntp = 0; ntp < 2; ntp++) {
                int r = b_r + ntp * 16;
                int ku = ku0 + b_ku;
                uint32_t off = (uint32_t)(r * 128 + ((ku ^ (r & 7)) << 4));
                ldsm4(bH[ntp], sBh + off);
                ldsm4(bL[ntp], sBl + off);
            }
#pragma unroll
            for (int mt = 0; mt < 2; mt++) {
#pragma unroll
                for (int nt = 0; nt < 4; nt++) {
                    const int ntp = nt >> 1;
                    const int sel = nt & 1;
                    mma16816(acc[mt][nt], aH[mt], bH[ntp][sel], bH[ntp][sel + 2]);
                    mma16816(acc[mt][nt], aH[mt], bL[ntp][sel], bL[ntp][sel + 2]);
                    mma16816(acc[mt][nt], aL[mt], bH[ntp][sel], bH[ntp][sel + 2]);
                }
            }
        }
        if (++buf == 3) buf = 0;
    }

    // Epilogue
#pragma unroll
    for (int mt = 0; mt < 2; mt++) {
        const int row = bm + wm * 32 + mt * 16 + (lane >> 2);
#pragma unroll
        for (int nt = 0; nt < 4; nt++) {
            const int col = bn + wn * 32 + nt * 8 + (lane & 3) * 2;
            if (C) {
                *(float2*)(C + (size_t)row * N + col) =
                    make_float2(acc[mt][nt][0], acc[mt][nt][1]);
                *(float2*)(C + (size_t)(row + 8) * N + col) =
                    make_float2(acc[mt][nt][2], acc[mt][nt][3]);
            } else {
                __nv_bfloat162 h, l;
                split2(acc[mt][nt][0], acc[mt][nt][1], &h, &l);
                *(__nv_bfloat162*)(Chi + (size_t)row * N + col) = h;
                *(__nv_bfloat162*)(Clo + (size_t)row * N + col) = l;
                split2(acc[mt][nt][2], acc[mt][nt][3], &h, &l);
                *(__nv_bfloat162*)(Chi + (size_t)(row + 8) * N + col) = h;
                *(__nv_bfloat162*)(Clo + (size_t)(row + 8) * N + col) = l;
            }
        }
    }
}

// Q projection + folded Wo conversion.
// blockIdx.x < 32: GEMM tile. blockIdx.x in [32, 48): Wo split-convert slices.
__global__ __launch_bounds__(GTHREADS)
void gemm_q_cvtwo(
    const __nv_bfloat16* __restrict__ Ahi, const __nv_bfloat16* __restrict__ Alo,
    const __nv_bfloat16* __restrict__ Bhi, const __nv_bfloat16* __restrict__ Blo,
    float* __restrict__ C,
    const float* __restrict__ wo,
    __nv_bfloat16* __restrict__ woh, __nv_bfloat16* __restrict__ wol)
{
    extern __shared__ __align__(1024) char smem[];
    if (blockIdx.x < QDIM / 128) {
        gemm_core(Ahi, Alo, Bhi, Blo, C, nullptr, nullptr, QDIM, HID,
                  blockIdx.y * 128, blockIdx.x * 128, smem);
    } else {
        // 16 extra bx * 16 by = 256 slices over HID*QDIM = 16,777,216 elems
        const int sid = (blockIdx.x - QDIM / 128) * (int)gridDim.y + blockIdx.y;
        const size_t n_per = ((size_t)HID * QDIM) / 256;   // 65536
        const size_t base = (size_t)sid * n_per;
        for (size_t i = base + threadIdx.x * 4; i < base + n_per;
             i += (size_t)GTHREADS * 4) {
            float4 v = *(const float4*)(wo + i);
            __nv_bfloat162 h0, l0, h1, l1;
            split2(v.x, v.y, &h0, &l0);
            split2(v.z, v.w, &h1, &l1);
            *(__nv_bfloat162*)(woh + i)     = h0;
            *(__nv_bfloat162*)(woh + i + 2) = h1;
            *(__nv_bfloat162*)(wol + i)     = l0;
            *(__nv_bfloat162*)(wol + i + 2) = l1;
        }
    }
}

// Plain GEMM kernel (O-proj)
__global__ __launch_bounds__(GTHREADS)
void gemm_bf16x3(
    const __nv_bfloat16* __restrict__ Ahi, const __nv_bfloat16* __restrict__ Alo,
    const __nv_bfloat16* __restrict__ Bhi, const __nv_bfloat16* __restrict__ Blo,
    float* __restrict__ C,
    __nv_bfloat16* __restrict__ Chi, __nv_bfloat16* __restrict__ Clo,
    int N, int K)
{
    extern __shared__ __align__(1024) char smem[];
    gemm_core(Ahi, Alo, Bhi, Blo, C, Chi, Clo, N, K,
              blockIdx.y * 128, blockIdx.x * 128, smem);
}

// Fused K+V projection: blockIdx.x < 8 -> K (fp32 out), else V (split out)
__global__ __launch_bounds__(GTHREADS)
void gemm_kv(
    const __nv_bfloat16* __restrict__ Ahi, const __nv_bfloat16* __restrict__ Alo,
    const __nv_bfloat16* __restrict__ Bkh, const __nv_bfloat16* __restrict__ Bkl,
    const __nv_bfloat16* __restrict__ Bvh, const __nv_bfloat16* __restrict__ Bvl,
    float* __restrict__ Ck,
    __nv_bfloat16* __restrict__ Cvh, __nv_bfloat16* __restrict__ Cvl)
{
    extern __shared__ __align__(1024) char smem[];
    const int bx = blockIdx.x;
    if (bx < KVDIM / 128) {
        gemm_core(Ahi, Alo, Bkh, Bkl, Ck, nullptr, nullptr, KVDIM, HID,
                  blockIdx.y * 128, bx * 128, smem);
    } else {
        gemm_core(Ahi, Alo, Bvh, Bvl, nullptr, Cvh, Cvl, KVDIM, HID,
                  blockIdx.y * 128, (bx - KVDIM / 128) * 128, smem);
    }
}

// ---------------------------------------------------------------------------
// Fused RMSNorm + RoPE for BOTH Q and K in one launch, bf16 hi/lo out.
// ---------------------------------------------------------------------------
#define RMS_BLOCKS (8192 + 2048)

__global__ __launch_bounds__(256) void rms_both(
    const float* __restrict__ Qf, const float* __restrict__ Kf,
    const float* __restrict__ qw, const float* __restrict__ kw,
    const float* __restrict__ cosb, const float* __restrict__ sinb,
    __nv_bfloat16* __restrict__ qh, __nv_bfloat16* __restrict__ ql,
    __nv_bfloat16* __restrict__ kh, __nv_bfloat16* __restrict__ kl)
{
    const int b = blockIdx.x;
    const float* X;
    const float* w;
    __nv_bfloat16 *oh, *ol;
    int nheads, row;
    if (b < 8192) { X = Qf; w = qw; oh = qh; ol = ql; nheads = NH;  row = b * 8; }
    else          { X = Kf; w = kw; oh = kh; ol = kl; nheads = NKV; row = (b - 8192) * 8; }
    row += threadIdx.x >> 5;
    const int lane = threadIdx.x & 31;
    const int s = row / nheads;

    const float* x = X + (size_t)row * HD;
    float4 v = *(const float4*)(x + lane * 4);

    float ss = v.x * v.x + v.y * v.y + v.z * v.z + v.w * v.w;
#pragma unroll
    for (int o = 16; o > 0; o >>= 1) ss += __shfl_xor_sync(0xffffffffu, ss, o);
    const float inv = rsqrtf(ss * (1.0f / 128.0f) + REPS);

    float4 wv = *(const float4*)(w + lane * 4);
    float x0 = v.x * inv * wv.x;
    float x1 = v.y * inv * wv.y;
    float x2 = v.z * inv * wv.z;
    float x3 = v.w * inv * wv.w;

    float p0 = __shfl_xor_sync(0xffffffffu, x0, 16);
    float p1 = __shfl_xor_sync(0xffffffffu, x1, 16);
    float p2 = __shfl_xor_sync(0xffffffffu, x2, 16);
    float p3 = __shfl_xor_sync(0xffffffffu, x3, 16);
    const float sgn = (lane < 16) ? -1.0f : 1.0f;

    const float* cp = cosb + (size_t)s * HD + lane * 4;
    const float* sp = sinb + (size_t)s * HD + lane * 4;
    float4 c = *(const float4*)cp;
    float4 sn = *(const float4*)sp;

    float o0 = x0 * c.x + sgn * p0 * sn.x;
    float o1 = x1 * c.y + sgn * p1 * sn.y;
    float o2 = x2 * c.z + sgn * p2 * sn.z;
    float o3 = x3 * c.w + sgn * p3 * sn.w;

    __nv_bfloat162 h, l;
    size_t base = (size_t)row * HD + lane * 4;
    split2(o0, o1, &h, &l);
    *(__nv_bfloat162*)(oh + base)     = h;
    *(__nv_bfloat162*)(ol + base)     = l;
    split2(o2, o3, &h, &l);
    *(__nv_bfloat162*)(oh + base + 2) = h;
    *(__nv_bfloat162*)(ol + base + 2) = l;
}

// ---------------------------------------------------------------------------
// Tensor-core flash attention (bf16 split), causal, GQA, 3-stage pipeline,
// single sync per KV block, warp-level skip of fully-masked blocks.
// Writes AO directly as bf16 hi/lo split.
// ---------------------------------------------------------------------------
#define KVTILE_B 16384                    // 64 rows x 256B
#define ASTAGE_B (4 * KVTILE_B)           // Kh,Kl,Vh,Vl
#define ASM_TOTAL (3 * ASTAGE_B)          // 196608

__device__ __forceinline__ uint32_t swz256(int r, int u) {
    return (uint32_t)(r * 256 + ((u ^ (r & 7)) << 4));
}

__device__ __forceinline__ void attn_load_kv(
    uint32_t base, const __nv_bfloat16* __restrict__ Kh,
    const __nv_bfloat16* __restrict__ Kl, const __nv_bfloat16* __restrict__ Vh,
    const __nv_bfloat16* __restrict__ Vl, int k0, int kvh, int tid)
{
#pragma unroll
    for (int t = 0; t < 4; t++) {
        int idx = tid + t * 256;
        int r = idx >> 4, u = idx & 15;
        size_t go = (size_t)(k0 + r) * KVDIM + kvh * HD + u * 8;
        uint32_t sw = swz256(r, u);
        asm volatile("cp.async.cg.shared.global [%0], [%1], 16;"
                     :: "r"(base + sw), "l"(Kh + go) : "memory");
        asm volatile("cp.async.cg.shared.global [%0], [%1], 16;"
                     :: "r"(base + KVTILE_B + sw), "l"(Kl + go) : "memory");
        asm volatile("cp.async.cg.shared.global [%0], [%1], 16;"
                     :: "r"(base + 2 * KVTILE_B + sw), "l"(Vh + go) : "memory");
        asm volatile("cp.async.cg.shared.global [%0], [%1], 16;"
                     :: "r"(base + 3 * KVTILE_B + sw), "l"(Vl + go) : "memory");
    }
}

__global__ __launch_bounds__(256, 1)
void attn_mma(const __nv_bfloat16* __restrict__ Qh, const __nv_bfloat16* __restrict__ Ql,
              const __nv_bfloat16* __restrict__ Kh, const __nv_bfloat16* __restrict__ Kl,
              const __nv_bfloat16* __restrict__ Vh, const __nv_bfloat16* __restrict__ Vl,
              __nv_bfloat16* __restrict__ Ohi, __nv_bfloat16* __restrict__ Olo)
{
    extern __shared__ __align__(1024) char smem[];
    const uint32_t sb = smem_u32(smem);
    const int tid  = threadIdx.x;
    const int lane = tid & 31;
    const int warp = tid >> 5;
    const int qb = (int)gridDim.x - 1 - (int)blockIdx.x;
    const int h  = blockIdx.y;
    const int kvh = h >> 2;
    const int q0 = qb * 128;
    const int NB = 2 * qb + 2;

    // ---- Stage Q through smem, build register fragments (hi then lo)
    uint32_t qfh[8][4], qfl[8][4];
#pragma unroll
    for (int comp = 0; comp < 2; comp++) {
        const __nv_bfloat16* src = comp ? Ql : Qh;
        for (int t = 0; t < 8; t++) {
            int idx = tid + t * 256;
            int r = idx >> 4, u = idx & 15;
            const __nv_bfloat16* gp = src + (size_t)(q0 + r) * QDIM + h * HD + u * 8;
            asm volatile("cp.async.cg.shared.global [%0], [%1], 16;"
                         :: "r"(sb + swz256(r, u)), "l"(gp) : "memory");
        }
        asm volatile("cp.async.commit_group;" ::: "memory");
        asm volatile("cp.async.wait_group 0;" ::: "memory");
        __syncthreads();
        {
            int r = warp * 16 + (lane & 15);
#pragma unroll
            for (int ks = 0; ks < 8; ks++) {
                uint32_t addr = sb + swz256(r, 2 * ks + (lane >> 4));
                if (comp) ldsm4(qfl[ks], addr);
                else      ldsm4(qfh[ks], addr);
            }
        }
        __syncthreads();
    }

    float o[16][4];
#pragma unroll
    for (int i = 0; i < 16; i++)
#pragma unroll
        for (int q = 0; q < 4; q++) o[i][q] = 0.0f;
    float m0 = -1e30f, m1 = -1e30f, l0 = 0.0f, l1 = 0.0f;

    const int row0 = q0 + warp * 16 + (lane >> 2);
    const int row1 = row0 + 8;
    const int row_top = q0 + warp * 16 + 15;   // max row owned by this warp

    // ---- prologue: stages 0 and 1
    attn_load_kv(sb, Kh, Kl, Vh, Vl, 0, kvh, tid);
    asm volatile("cp.async.commit_group;" ::: "memory");
    if (NB > 1) {
        attn_load_kv(sb + ASTAGE_B, Kh, Kl, Vh, Vl, 64, kvh, tid);
        asm volatile("cp.async.commit_group;" ::: "memory");
    }

    int buf = 0;
    for (int kb = 0; kb < NB; kb++) {
        if (kb + 1 < NB)
            asm volatile("cp.async.wait_group 1;" ::: "memory");
        else
            asm volatile("cp.async.wait_group 0;" ::: "memory");
        __syncthreads();   // block kb visible AND all warps done with block kb-1

        if (kb + 2 < NB) {
            int nb = buf + 2; if (nb >= 3) nb -= 3;
            attn_load_kv(sb + nb * ASTAGE_B, Kh, Kl, Vh, Vl, (kb + 2) * 64, kvh, tid);
            asm volatile("cp.async.commit_group;" ::: "memory");
        }

        const uint32_t bK = sb + buf * ASTAGE_B;
        const int k0 = kb * 64;

        if (k0 <= row_top) {   // skip fully-masked blocks (exact: P would be 0)

        // ---- S = Q K^T (bf16x3)
        float s[8][4];
#pragma unroll
        for (int nt = 0; nt < 8; nt++)
#pragma unroll
            for (int q = 0; q < 4; q++) s[nt][q] = 0.0f;

#pragma unroll
        for (int ks = 0; ks < 8; ks++) {
#pragma unroll
            for (int g = 0; g < 4; g++) {
                uint32_t kh4[4], kl4[4];
                int rr = g * 16 + ((lane >> 3) & 1) * 8 + (lane & 7);
                uint32_t off = swz256(rr, 2 * ks + (lane >> 4));
                ldsm4(kh4, bK + off);
                ldsm4(kl4, bK + KVTILE_B + off);
#pragma unroll
                for (int sel = 0; sel < 2; sel++) {
                    int nt = g * 2 + sel;
                    mma16816(s[nt], qfh[ks], kh4[sel], kh4[sel + 2]);
                    mma16816(s[nt], qfh[ks], kl4[sel], kl4[sel + 2]);
                    mma16816(s[nt], qfl[ks], kh4[sel], kh4[sel + 2]);
                }
            }
        }

        // ---- scale + causal mask
        const bool domask = (k0 + 63) > row0;
#pragma unroll
        for (int nt = 0; nt < 8; nt++) {
            int c0 = k0 + nt * 8 + (lane & 3) * 2;
#pragma unroll
            for (int q = 0; q < 4; q++) s[nt][q] *= RSCALE;
            if (domask) {
                if (c0     > row0) s[nt][0] = -1e30f;
                if (c0 + 1 > row0) s[nt][1] = -1e30f;
                if (c0     > row1) s[nt][2] = -1e30f;
                if (c0 + 1 > row1) s[nt][3] = -1e30f;
            }
        }

        // ---- online softmax
        float mx0 = -1e30f, mx1 = -1e30f;
#pragma unroll
        for (int nt = 0; nt < 8; nt++) {
            mx0 = fmaxf(mx0, fmaxf(s[nt][0], s[nt][1]));
            mx1 = fmaxf(mx1, fmaxf(s[nt][2], s[nt][3]));
        }
        mx0 = fmaxf(mx0, __shfl_xor_sync(0xffffffffu, mx0, 1));
        mx0 = fmaxf(mx0, __shfl_xor_sync(0xffffffffu, mx0, 2));
        mx1 = fmaxf(mx1, __shfl_xor_sync(0xffffffffu, mx1, 1));
        mx1 = fmaxf(mx1, __shfl_xor_sync(0xffffffffu, mx1, 2));

        float mn0 = fmaxf(m0, mx0), mn1 = fmaxf(m1, mx1);
        float a0 = __expf(m0 - mn0), a1 = __expf(m1 - mn1);
        m0 = mn0; m1 = mn1;

        float sum0 = 0.0f, sum1 = 0.0f;
#pragma unroll
        for (int nt = 0; nt < 8; nt++) {
            s[nt][0] = __expf(s[nt][0] - mn0);
            s[nt][1] = __expf(s[nt][1] - mn0);
            s[nt][2] = __expf(s[nt][2] - mn1);
            s[nt][3] = __expf(s[nt][3] - mn1);
            sum0 += s[nt][0] + s[nt][1];
            sum1 += s[nt][2] + s[nt][3];
        }
        sum0 += __shfl_xor_sync(0xffffffffu, sum0, 1);
        sum0 += __shfl_xor_sync(0xffffffffu, sum0, 2);
        sum1 += __shfl_xor_sync(0xffffffffu, sum1, 1);
        sum1 += __shfl_xor_sync(0xffffffffu, sum1, 2);
        l0 = l0 * a0 + sum0;
        l1 = l1 * a1 + sum1;

#pragma unroll
        for (int nt = 0; nt < 16; nt++) {
            o[nt][0] *= a0; o[nt][1] *= a0;
            o[nt][2] *= a1; o[nt][3] *= a1;
        }

        // ---- O += P V (bf16 split P and V)
#pragma unroll
        for (int kt = 0; kt < 4; kt++) {
            uint32_t pah[4], pal[4];
            {
                float e[8] = { s[2*kt][0], s[2*kt][1], s[2*kt][2], s[2*kt][3],
                               s[2*kt+1][0], s[2*kt+1][1], s[2*kt+1][2], s[2*kt+1][3] };
                float hf[8], lf[8];
#pragma unroll
                for (int q = 0; q < 8; q++) {
                    __nv_bfloat16 hb = __float2bfloat16(e[q]);
                    hf[q] = __bfloat162float(hb);
                    lf[q] = e[q] - hf[q];
                }
                pah[0] = pack_bf16(hf[0], hf[1]);
                pah[1] = pack_bf16(hf[2], hf[3]);
                pah[2] = pack_bf16(hf[4], hf[5]);
                pah[3] = pack_bf16(hf[6], hf[7]);
                pal[0] = pack_bf16(lf[0], lf[1]);
                pal[1] = pack_bf16(lf[2], lf[3]);
                pal[2] = pack_bf16(lf[4], lf[5]);
                pal[3] = pack_bf16(lf[6], lf[7]);
            }
            const int j = lane >> 3, ll = lane & 7;
            const int rr = kt * 16 + (j & 1) * 8 + ll;
#pragma unroll
            for (int gn = 0; gn < 8; gn++) {
                uint32_t vh4[4], vl4[4];
                uint32_t off = swz256(rr, gn * 2 + (j >> 1));
                ldsm4t(vh4, bK + 2 * KVTILE_B + off);
                ldsm4t(vl4, bK + 3 * KVTILE_B + off);
#pragma unroll
                for (int sel = 0; sel < 2; sel++) {
                    int nt = gn * 2 + sel;
                    mma16816(o[nt], pah, vh4[sel * 2], vh4[sel * 2 + 1]);
                    mma16816(o[nt], pah, vl4[sel * 2], vl4[sel * 2 + 1]);
                    mma16816(o[nt], pal, vh4[sel * 2], vh4[sel * 2 + 1]);
                }
            }
        }

        }  // end fully-masked skip

        if (++buf == 3) buf = 0;
    }

    // ---- finalize: write split AO directly
    const float i0 = 1.0f / l0, i1 = 1.0f / l1;
#pragma unroll
    for (int nt = 0; nt < 16; nt++) {
        int col = h * HD + nt * 8 + (lane & 3) * 2;
        __nv_bfloat162 hh, ll2;
        split2(o[nt][0] * i0, o[nt][1] * i0, &hh, &ll2);
        *(__nv_bfloat162*)(Ohi + (size_t)row0 * QDIM + col) = hh;
        *(__nv_bfloat162*)(Olo + (size_t)row0 * QDIM + col) = ll2;
        split2(o[nt][2] * i1, o[nt][3] * i1, &hh, &ll2);
        *(__nv_bfloat162*)(Ohi + (size_t)row1 * QDIM + col) = hh;
        *(__nv_bfloat162*)(Olo + (size_t)row1 * QDIM + col) = ll2;
    }
}

// ---------------------------------------------------------------------------
extern "C" void kernel_launch(void* const* d_in, const int* in_sizes, int n_in,
                              void* d_out, int out_size)
{
    const float* hidden = (const float*)d_in[0];
    const float* cosb   = (const float*)d_in[1];
    const float* sinb   = (const float*)d_in[2];
    const float* Wq     = (const float*)d_in[3];
    const float* Wk     = (const float*)d_in[4];
    const float* Wv     = (const float*)d_in[5];
    const float* Wo     = (const float*)d_in[6];
    const float* qw     = (const float*)d_in[7];
    const float* kw     = (const float*)d_in[8];
    float* out = (float*)d_out;

    float *Qp, *Kp;
    cudaGetSymbolAddress((void**)&Qp,  g_Q);
    cudaGetSymbolAddress((void**)&Kp,  g_K);

    __nv_bfloat16 *Xh, *Xl, *Wqh, *Wql, *Wkh, *Wkl, *Wvh, *Wvl, *Woh, *Wol, *AOh, *AOl;
    __nv_bfloat16 *Qh2, *Ql2, *Kh2, *Kl2, *Vh2, *Vl2;
    cudaGetSymbolAddress((void**)&Xh,  g_Xhi);  cudaGetSymbolAddress((void**)&Xl,  g_Xlo);
    cudaGetSymbolAddress((void**)&Wqh, g_Wqh);  cudaGetSymbolAddress((void**)&Wql, g_Wql);
    cudaGetSymbolAddress((void**)&Wkh, g_Wkh);  cudaGetSymbolAddress((void**)&Wkl, g_Wkl);
    cudaGetSymbolAddress((void**)&Wvh, g_Wvh);  cudaGetSymbolAddress((void**)&Wvl, g_Wvl);
    cudaGetSymbolAddress((void**)&Woh, g_Woh);  cudaGetSymbolAddress((void**)&Wol, g_Wol);
    cudaGetSymbolAddress((void**)&AOh, g_AOh);  cudaGetSymbolAddress((void**)&AOl, g_AOl);
    cudaGetSymbolAddress((void**)&Qh2, g_Qh2);  cudaGetSymbolAddress((void**)&Ql2, g_Ql2);
    cudaGetSymbolAddress((void**)&Kh2, g_Kh2);  cudaGetSymbolAddress((void**)&Kl2, g_Kl2);
    cudaGetSymbolAddress((void**)&Vh2, g_Vh2);  cudaGetSymbolAddress((void**)&Vl2, g_Vl2);

    cudaFuncSetAttribute(gemm_q_cvtwo,
                         cudaFuncAttributeMaxDynamicSharedMemorySize, GSM_TOTAL);
    cudaFuncSetAttribute(gemm_bf16x3,
                         cudaFuncAttributeMaxDynamicSharedMemorySize, GSM_TOTAL);
    cudaFuncSetAttribute(gemm_kv,
                         cudaFuncAttributeMaxDynamicSharedMemorySize, GSM_TOTAL);
    cudaFuncSetAttribute(attn_mma,
                         cudaFuncAttributeMaxDynamicSharedMemorySize, ASM_TOTAL);

    // L0: split conversions for X, Wq, Wk, Wv (Wo folded into L1)
    cvt_all<<<CVT_BLOCKS, 256>>>(hidden, Xh, Xl, Wq, Wqh, Wql, Wk, Wkh, Wkl,
                                 Wv, Wvh, Wvl);

    // L1: Q projection + Wo split conversion
    gemm_q_cvtwo<<<dim3(QDIM / 128 + 16, SEQ / 128), GTHREADS, GSM_TOTAL>>>(
        Xh, Xl, Wqh, Wql, Qp, Wo, Woh, Wol);

    // L2: fused K+V projection
    gemm_kv<<<dim3(2 * KVDIM / 128, SEQ / 128), GTHREADS, GSM_TOTAL>>>(
        Xh, Xl, Wkh, Wkl, Wvh, Wvl, Kp, Vh2, Vl2);

    // L3: RMSNorm + RoPE for Q and K in one launch
    rms_both<<<RMS_BLOCKS, 256>>>(Qp, Kp, qw, kw, cosb, sinb,
                                  Qh2, Ql2, Kh2, Kl2);

    // L4: tensor-core flash attention -> split AO
    attn_mma<<<dim3(SEQ / 128, NH), 256, ASM_TOTAL>>>(
        Qh2, Ql2, Kh2, Kl2, Vh2, Vl2, AOh, AOl);

    // L5: output projection
    gemm_bf16x3<<<dim3(HID / 128, SEQ / 128), GTHREADS, GSM_TOTAL>>>(
        AOh, AOl, Woh, Wol, out, nullptr, nullptr, HID, QDIM);
}

// round 14
// speedup vs baseline: 1.6279x; 1.4134x over previous
#include <cuda_runtime.h>
#include <cuda_fp16.h>
#include <stdint.h>
#include <math.h>

// Problem constants (B=1)
#define SEQ   2048
#define HID   4096
#define NH    32
#define NKV   8
#define HD    128
#define QDIM  (NH * HD)   // 4096
#define KVDIM (NKV * HD)  // 1024
#define RSCALE 0.08838834764831845f  // 128^-0.5
#define REPS   1e-6f

// ---------------------------------------------------------------------------
// Scratch (__device__ globals: allocation-free rule)
// ---------------------------------------------------------------------------
__device__ float g_Q[SEQ * QDIM];
__device__ float g_K[SEQ * KVDIM];

__device__ __half g_Xh[SEQ * HID],   g_Xl[SEQ * HID];
__device__ __half g_Wqf[QDIM * HID];
__device__ __half g_Wkf[KVDIM * HID];
__device__ __half g_Wvf[KVDIM * HID];
__device__ __half g_Wof[HID * QDIM];
__device__ __half g_AOh[SEQ * QDIM], g_AOl[SEQ * QDIM];

__device__ __half g_Qh2[SEQ * QDIM], g_Ql2[SEQ * QDIM];
__device__ __half g_Kf2[SEQ * KVDIM];
__device__ __half g_Vf2[SEQ * KVDIM];

// ---------------------------------------------------------------------------
// PTX helpers (base sm_100-safe)
// ---------------------------------------------------------------------------
__device__ __forceinline__ uint32_t smem_u32(const void* p) {
    uint32_t a;
    asm("{ .reg .u64 t; cvta.to.shared.u64 t, %1; cvt.u32.u64 %0, t; }"
        : "=r"(a) : "l"(p));
    return a;
}

__device__ __forceinline__ void ldsm4(uint32_t* r, uint32_t addr) {
    asm volatile("ldmatrix.sync.aligned.m8n8.x4.shared.b16 {%0,%1,%2,%3}, [%4];"
                 : "=r"(r[0]), "=r"(r[1]), "=r"(r[2]), "=r"(r[3]) : "r"(addr));
}

__device__ __forceinline__ void ldsm4t(uint32_t* r, uint32_t addr) {
    asm volatile("ldmatrix.sync.aligned.m8n8.x4.trans.shared.b16 {%0,%1,%2,%3}, [%4];"
                 : "=r"(r[0]), "=r"(r[1]), "=r"(r[2]), "=r"(r[3]) : "r"(addr));
}

// fp16 inputs, fp32 accumulate
__device__ __forceinline__ void mma16816h(float* c, const uint32_t* a,
                                          uint32_t b0, uint32_t b1) {
    asm volatile(
        "mma.sync.aligned.m16n8k16.row.col.f32.f16.f16.f32 "
        "{%0,%1,%2,%3}, {%4,%5,%6,%7}, {%8,%9}, {%0,%1,%2,%3};"
        : "+f"(c[0]), "+f"(c[1]), "+f"(c[2]), "+f"(c[3])
        : "r"(a[0]), "r"(a[1]), "r"(a[2]), "r"(a[3]), "r"(b0), "r"(b1));
}

__device__ __forceinline__ uint32_t packh2(float lo, float hi) {
    __half2 t = __floats2half2_rn(lo, hi);
    return *(uint32_t*)&t;
}

// fp32 -> fp16 hi + fp16 lo residual
__device__ __forceinline__ void split2h(float a, float b,
                                        __half2* h, __half2* l) {
    __half ha = __float2half(a);
    __half hb = __float2half(b);
    h->x = ha; h->y = hb;
    l->x = __float2half(a - __half2float(ha));
    l->y = __float2half(b - __half2float(hb));
}

// ---------------------------------------------------------------------------
// Fused conversions: X -> fp16 split; Wq/Wk/Wv -> fp16 single.
//   X:  [0, 8192)   Wq: [8192, 24576)  Wk: [24576, 28672)  Wv: [28672, 32768)
// ---------------------------------------------------------------------------
#define CVT_BLOCKS 32768

__global__ __launch_bounds__(256) void cvt_all(
    const float* __restrict__ x,  __half* __restrict__ xh, __half* __restrict__ xl,
    const float* __restrict__ wq, __half* __restrict__ wqf,
    const float* __restrict__ wk, __half* __restrict__ wkf,
    const float* __restrict__ wv, __half* __restrict__ wvf)
{
    const int b = blockIdx.x;
    if (b < 8192) {
        const int i = (b * 256 + threadIdx.x) * 4;
        float4 v = *(const float4*)(x + i);
        __half2 h0, l0, h1, l1;
        split2h(v.x, v.y, &h0, &l0);
        split2h(v.z, v.w, &h1, &l1);
        *(__half2*)(xh + i)     = h0;
        *(__half2*)(xh + i + 2) = h1;
        *(__half2*)(xl + i)     = l0;
        *(__half2*)(xl + i + 2) = l1;
    } else {
        const float* src;
        __half* dst;
        int base;
        if (b < 24576)      { src = wq; dst = wqf; base = 8192; }
        else if (b < 28672) { src = wk; dst = wkf; base = 24576; }
        else                { src = wv; dst = wvf; base = 28672; }
        const int i = ((b - base) * 256 + threadIdx.x) * 4;
        float4 v = *(const float4*)(src + i);
        *(__half2*)(dst + i)     = __floats2half2_rn(v.x, v.y);
        *(__half2*)(dst + i + 2) = __floats2half2_rn(v.z, v.w);
    }
}

// ---------------------------------------------------------------------------
// mma.sync fp16x2 GEMM core: C = (Ahi+Alo)[M,K] * Bf[N,K]^T  (A exact-split,
// B single fp16). 512 threads, 128x128 CTA tile, BK=64, 3-stage pipeline.
// ---------------------------------------------------------------------------
#define GTHREADS 512
#define TILE_B   16384                 // 128 rows x 128B (64 fp16 cols)
#define GSTAGE_B (3 * TILE_B)          // Ah, Al, Bf
#define GSM_TOTAL (3 * GSTAGE_B)       // 147456

__device__ __forceinline__ void load_tile64(
    uint32_t sdst, const __half* __restrict__ g,
    int row0, int kc, int K, int tid)
{
#pragma unroll
    for (int s = 0; s < 2; s++) {
        int idx = tid + s * GTHREADS;
        int r = idx >> 3;
        int u = idx & 7;
        uint32_t sw = (uint32_t)(r * 128 + ((u ^ (r & 7)) << 4));
        const __half* gp = g + (size_t)(row0 + r) * K + kc * 64 + u * 8;
        asm volatile("cp.async.cg.shared.global [%0], [%1], 16;"
                     :: "r"(sdst + sw), "l"(gp) : "memory");
    }
}

__device__ __forceinline__ void gemm_core(
    const __half* __restrict__ Ahi, const __half* __restrict__ Alo,
    const __half* __restrict__ Bf,
    float* __restrict__ C, __half* __restrict__ Ch,
    int N, int K, int bm, int bn, char* smem)
{
    const uint32_t sb = smem_u32(smem);
    const int tid  = threadIdx.x;
    const int lane = tid & 31;
    const int warp = tid >> 5;
    const int wm = warp >> 2;
    const int wn = warp & 3;
    const int NC = K >> 6;

    float acc[2][4][4];
#pragma unroll
    for (int i = 0; i < 2; i++)
#pragma unroll
        for (int j = 0; j < 4; j++)
#pragma unroll
            for (int q = 0; q < 4; q++) acc[i][j][q] = 0.0f;

    // Prologue: stages 0 and 1
#pragma unroll
    for (int c = 0; c < 2; c++) {
        uint32_t b = sb + c * GSTAGE_B;
        load_tile64(b,              Ahi, bm, c, K, tid);
        load_tile64(b + TILE_B,     Alo, bm, c, K, tid);
        load_tile64(b + 2 * TILE_B, Bf,  bn, c, K, tid);
        asm volatile("cp.async.commit_group;" ::: "memory");
    }

    const int a_r  = wm * 32 + (lane & 15);
    const int a_ku = lane >> 4;
    const int b_r  = wn * 32 + ((lane >> 3) & 1) * 8 + (lane & 7);
    const int b_ku = lane >> 4;

    int buf = 0;
    for (int c = 0; c < NC; c++) {
        if (c + 1 < NC)
            asm volatile("cp.async.wait_group 1;" ::: "memory");
        else
            asm volatile("cp.async.wait_group 0;" ::: "memory");
        __syncthreads();

        if (c + 2 < NC) {
            int nb = buf + 2; if (nb >= 3) nb -= 3;
            uint32_t b2 = sb + nb * GSTAGE_B;
            load_tile64(b2,              Ahi, bm, c + 2, K, tid);
            load_tile64(b2 + TILE_B,     Alo, bm, c + 2, K, tid);
            load_tile64(b2 + 2 * TILE_B, Bf,  bn, c + 2, K, tid);
            asm volatile("cp.async.commit_group;" ::: "memory");
        }

        const uint32_t b = sb + buf * GSTAGE_B;
        const uint32_t sAh = b;
        const uint32_t sAl = b + TILE_B;
        const uint32_t sBf = b + 2 * TILE_B;

#pragma unroll
        for (int ks = 0; ks < 4; ks++) {
            const int ku0 = ks * 2;
            uint32_t aH[2][4], aL[2][4];
#pragma unroll
            for (int mt = 0; mt < 2; mt++) {
                int r = a_r + mt * 16;
                int ku = ku0 + a_ku;
                uint32_t off = (uint32_t)(r * 128 + ((ku ^ (r & 7)) << 4));
                ldsm4(aH[mt], sAh + off);
                ldsm4(aL[mt], sAl + off);
            }
            uint32_t bF[2][4];
#pragma unroll
            for (int ntp = 0; ntp < 2; ntp++) {
                int r = b_r + ntp * 16;
                int ku = ku0 + b_ku;
                uint32_t off = (uint32_t)(r * 128 + ((ku ^ (r & 7)) << 4));
                ldsm4(bF[ntp], sBf + off);
            }
#pragma unroll
            for (int mt = 0; mt < 2; mt++) {
#pragma unroll
                for (int nt = 0; nt < 4; nt++) {
                    const int ntp = nt >> 1;
                    const int sel = nt & 1;
                    mma16816h(acc[mt][nt], aH[mt], bF[ntp][sel], bF[ntp][sel + 2]);
                    mma16816h(acc[mt][nt], aL[mt], bF[ntp][sel], bF[ntp][sel + 2]);
                }
            }
        }
        if (++buf == 3) buf = 0;
    }

    // Epilogue: fp32 (C) or fp16-single (Ch)
#pragma unroll
    for (int mt = 0; mt < 2; mt++) {
        const int row = bm + wm * 32 + mt * 16 + (lane >> 2);
#pragma unroll
        for (int nt = 0; nt < 4; nt++) {
            const int col = bn + wn * 32 + nt * 8 + (lane & 3) * 2;
            if (C) {
                *(float2*)(C + (size_t)row * N + col) =
                    make_float2(acc[mt][nt][0], acc[mt][nt][1]);
                *(float2*)(C + (size_t)(row + 8) * N + col) =
                    make_float2(acc[mt][nt][2], acc[mt][nt][3]);
            } else {
                *(__half2*)(Ch + (size_t)row * N + col) =
                    __floats2half2_rn(acc[mt][nt][0], acc[mt][nt][1]);
                *(__half2*)(Ch + (size_t)(row + 8) * N + col) =
                    __floats2half2_rn(acc[mt][nt][2], acc[mt][nt][3]);
            }
        }
    }
}

// Q projection + folded Wo single-conversion.
__global__ __launch_bounds__(GTHREADS)
void gemm_q_cvtwo(
    const __half* __restrict__ Ahi, const __half* __restrict__ Alo,
    const __half* __restrict__ Bf, float* __restrict__ C,
    const float* __restrict__ wo, __half* __restrict__ wof)
{
    extern __shared__ __align__(1024) char smem[];
    if (blockIdx.x < QDIM / 128) {
        gemm_core(Ahi, Alo, Bf, C, nullptr, QDIM, HID,
                  blockIdx.y * 128, blockIdx.x * 128, smem);
    } else {
        const int sid = (blockIdx.x - QDIM / 128) * (int)gridDim.y + blockIdx.y;
        const size_t n_per = ((size_t)HID * QDIM) / 256;   // 65536
        const size_t base = (size_t)sid * n_per;
        for (size_t i = base + threadIdx.x * 4; i < base + n_per;
             i += (size_t)GTHREADS * 4) {
            float4 v = *(const float4*)(wo + i);
            *(__half2*)(wof + i)     = __floats2half2_rn(v.x, v.y);
            *(__half2*)(wof + i + 2) = __floats2half2_rn(v.z, v.w);
        }
    }
}

// O projection
__global__ __launch_bounds__(GTHREADS)
void gemm_o(const __half* __restrict__ Ahi, const __half* __restrict__ Alo,
            const __half* __restrict__ Bf, float* __restrict__ C)
{
    extern __shared__ __align__(1024) char smem[];
    gemm_core(Ahi, Alo, Bf, C, nullptr, HID, QDIM,
              blockIdx.y * 128, blockIdx.x * 128, smem);
}

// Fused K+V projection: bx < 8 -> K (fp32 out), else V (fp16 single out)
__global__ __launch_bounds__(GTHREADS)
void gemm_kv(const __half* __restrict__ Ahi, const __half* __restrict__ Alo,
             const __half* __restrict__ Bkf, const __half* __restrict__ Bvf,
             float* __restrict__ Ck, __half* __restrict__ Cvf)
{
    extern __shared__ __align__(1024) char smem[];
    const int bx = blockIdx.x;
    if (bx < KVDIM / 128) {
        gemm_core(Ahi, Alo, Bkf, Ck, nullptr, KVDIM, HID,
                  blockIdx.y * 128, bx * 128, smem);
    } else {
        gemm_core(Ahi, Alo, Bvf, nullptr, Cvf, KVDIM, HID,
                  blockIdx.y * 128, (bx - KVDIM / 128) * 128, smem);
    }
}

// ---------------------------------------------------------------------------
// Fused RMSNorm + RoPE. Q -> fp16 split (qh, ql); K -> fp16 single (kf).
// ---------------------------------------------------------------------------
#define RMS_BLOCKS (8192 + 2048)

__global__ __launch_bounds__(256) void rms_both(
    const float* __restrict__ Qf, const float* __restrict__ Kf,
    const float* __restrict__ qw, const float* __restrict__ kw,
    const float* __restrict__ cosb, const float* __restrict__ sinb,
    __half* __restrict__ qh, __half* __restrict__ ql,
    __half* __restrict__ kf)
{
    const int b = blockIdx.x;
    const float* X;
    const float* w;
    int nheads, row;
    bool isq;
    if (b < 8192) { X = Qf; w = qw; nheads = NH;  row = b * 8; isq = true; }
    else          { X = Kf; w = kw; nheads = NKV; row = (b - 8192) * 8; isq = false; }
    row += threadIdx.x >> 5;
    const int lane = threadIdx.x & 31;
    const int s = row / nheads;

    const float* x = X + (size_t)row * HD;
    float4 v = *(const float4*)(x + lane * 4);

    float ss = v.x * v.x + v.y * v.y + v.z * v.z + v.w * v.w;
#pragma unroll
    for (int o = 16; o > 0; o >>= 1) ss += __shfl_xor_sync(0xffffffffu, ss, o);
    const float inv = rsqrtf(ss * (1.0f / 128.0f) + REPS);

    float4 wv = *(const float4*)(w + lane * 4);
    float x0 = v.x * inv * wv.x;
    float x1 = v.y * inv * wv.y;
    float x2 = v.z * inv * wv.z;
    float x3 = v.w * inv * wv.w;

    float p0 = __shfl_xor_sync(0xffffffffu, x0, 16);
    float p1 = __shfl_xor_sync(0xffffffffu, x1, 16);
    float p2 = __shfl_xor_sync(0xffffffffu, x2, 16);
    float p3 = __shfl_xor_sync(0xffffffffu, x3, 16);
    const float sgn = (lane < 16) ? -1.0f : 1.0f;

    const float* cp = cosb + (size_t)s * HD + lane * 4;
    const float* sp = sinb + (size_t)s * HD + lane * 4;
    float4 c = *(const float4*)cp;
    float4 sn = *(const float4*)sp;

    float o0 = x0 * c.x + sgn * p0 * sn.x;
    float o1 = x1 * c.y + sgn * p1 * sn.y;
    float o2 = x2 * c.z + sgn * p2 * sn.z;
    float o3 = x3 * c.w + sgn * p3 * sn.w;

    size_t base = (size_t)row * HD + lane * 4;
    if (isq) {
        __half2 h, l;
        split2h(o0, o1, &h, &l);
        *(__half2*)(qh + base)     = h;
        *(__half2*)(ql + base)     = l;
        split2h(o2, o3, &h, &l);
        *(__half2*)(qh + base + 2) = h;
        *(__half2*)(ql + base + 2) = l;
    } else {
        *(__half2*)(kf + base)     = __floats2half2_rn(o0, o1);
        *(__half2*)(kf + base + 2) = __floats2half2_rn(o2, o3);
    }
}

// ---------------------------------------------------------------------------
// Tensor-core flash attention (fp16), causal, GQA, 3-stage pipeline,
// warp-level skip of fully-masked blocks. Q split (exact), K/V single fp16,
// P split (exact). Writes AO as fp16 hi/lo split.
// ---------------------------------------------------------------------------
#define KVTILE_B 16384                    // 64 rows x 256B
#define ASTAGE_B (2 * KVTILE_B)           // Kf, Vf
#define ASM_TOTAL (3 * ASTAGE_B)          // 98304

__device__ __forceinline__ uint32_t swz256(int r, int u) {
    return (uint32_t)(r * 256 + ((u ^ (r & 7)) << 4));
}

__device__ __forceinline__ void attn_load_kv(
    uint32_t base, const __half* __restrict__ Kf,
    const __half* __restrict__ Vf, int k0, int kvh, int tid)
{
#pragma unroll
    for (int t = 0; t < 4; t++) {
        int idx = tid + t * 256;
        int r = idx >> 4, u = idx & 15;
        size_t go = (size_t)(k0 + r) * KVDIM + kvh * HD + u * 8;
        uint32_t sw = swz256(r, u);
        asm volatile("cp.async.cg.shared.global [%0], [%1], 16;"
                     :: "r"(base + sw), "l"(Kf + go) : "memory");
        asm volatile("cp.async.cg.shared.global [%0], [%1], 16;"
                     :: "r"(base + KVTILE_B + sw), "l"(Vf + go) : "memory");
    }
}

__global__ __launch_bounds__(256, 1)
void attn_mma(const __half* __restrict__ Qh, const __half* __restrict__ Ql,
              const __half* __restrict__ Kf, const __half* __restrict__ Vf,
              __half* __restrict__ Ohi, __half* __restrict__ Olo)
{
    extern __shared__ __align__(1024) char smem[];
    const uint32_t sb = smem_u32(smem);
    const int tid  = threadIdx.x;
    const int lane = tid & 31;
    const int warp = tid >> 5;
    const int qb = (int)gridDim.x - 1 - (int)blockIdx.x;
    const int h  = blockIdx.y;
    const int kvh = h >> 2;
    const int q0 = qb * 128;
    const int NB = 2 * qb + 2;

    // ---- Stage Q through smem, build register fragments (hi then lo)
    uint32_t qfh[8][4], qfl[8][4];
#pragma unroll
    for (int comp = 0; comp < 2; comp++) {
        const __half* src = comp ? Ql : Qh;
        for (int t = 0; t < 8; t++) {
            int idx = tid + t * 256;
            int r = idx >> 4, u = idx & 15;
            const __half* gp = src + (size_t)(q0 + r) * QDIM + h * HD + u * 8;
            asm volatile("cp.async.cg.shared.global [%0], [%1], 16;"
                         :: "r"(sb + swz256(r, u)), "l"(gp) : "memory");
        }
        asm volatile("cp.async.commit_group;" ::: "memory");
        asm volatile("cp.async.wait_group 0;" ::: "memory");
        __syncthreads();
        {
            int r = warp * 16 + (lane & 15);
#pragma unroll
            for (int ks = 0; ks < 8; ks++) {
                uint32_t addr = sb + swz256(r, 2 * ks + (lane >> 4));
                if (comp) ldsm4(qfl[ks], addr);
                else      ldsm4(qfh[ks], addr);
            }
        }
        __syncthreads();
    }

    float o[16][4];
#pragma unroll
    for (int i = 0; i < 16; i++)
#pragma unroll
        for (int q = 0; q < 4; q++) o[i][q] = 0.0f;
    float m0 = -1e30f, m1 = -1e30f, l0 = 0.0f, l1 = 0.0f;

    const int row0 = q0 + warp * 16 + (lane >> 2);
    const int row1 = row0 + 8;
    const int row_top = q0 + warp * 16 + 15;

    // ---- prologue: stages 0 and 1
    attn_load_kv(sb, Kf, Vf, 0, kvh, tid);
    asm volatile("cp.async.commit_group;" ::: "memory");
    if (NB > 1) {
        attn_load_kv(sb + ASTAGE_B, Kf, Vf, 64, kvh, tid);
        asm volatile("cp.async.commit_group;" ::: "memory");
    }

    int buf = 0;
    for (int kb = 0; kb < NB; kb++) {
        if (kb + 1 < NB)
            asm volatile("cp.async.wait_group 1;" ::: "memory");
        else
            asm volatile("cp.async.wait_group 0;" ::: "memory");
        __syncthreads();

        if (kb + 2 < NB) {
            int nb = buf + 2; if (nb >= 3) nb -= 3;
            attn_load_kv(sb + nb * ASTAGE_B, Kf, Vf, (kb + 2) * 64, kvh, tid);
            asm volatile("cp.async.commit_group;" ::: "memory");
        }

        const uint32_t bK = sb + buf * ASTAGE_B;
        const int k0 = kb * 64;

        if (k0 <= row_top) {   // skip fully-masked blocks (exact)

        // ---- S = Q K^T (fp16, Q exact-split)
        float s[8][4];
#pragma unroll
        for (int nt = 0; nt < 8; nt++)
#pragma unroll
            for (int q = 0; q < 4; q++) s[nt][q] = 0.0f;

#pragma unroll
        for (int ks = 0; ks < 8; ks++) {
#pragma unroll
            for (int g = 0; g < 4; g++) {
                uint32_t kf4[4];
                int rr = g * 16 + ((lane >> 3) & 1) * 8 + (lane & 7);
                uint32_t off = swz256(rr, 2 * ks + (lane >> 4));
                ldsm4(kf4, bK + off);
#pragma unroll
                for (int sel = 0; sel < 2; sel++) {
                    int nt = g * 2 + sel;
                    mma16816h(s[nt], qfh[ks], kf4[sel], kf4[sel + 2]);
                    mma16816h(s[nt], qfl[ks], kf4[sel], kf4[sel + 2]);
                }
            }
        }

        // ---- scale + causal mask
        const bool domask = (k0 + 63) > row0;
#pragma unroll
        for (int nt = 0; nt < 8; nt++) {
            int c0 = k0 + nt * 8 + (lane & 3) * 2;
#pragma unroll
            for (int q = 0; q < 4; q++) s[nt][q] *= RSCALE;
            if (domask) {
                if (c0     > row0) s[nt][0] = -1e30f;
                if (c0 + 1 > row0) s[nt][1] = -1e30f;
                if (c0     > row1) s[nt][2] = -1e30f;
                if (c0 + 1 > row1) s[nt][3] = -1e30f;
            }
        }

        // ---- online softmax
        float mx0 = -1e30f, mx1 = -1e30f;
#pragma unroll
        for (int nt = 0; nt < 8; nt++) {
            mx0 = fmaxf(mx0, fmaxf(s[nt][0], s[nt][1]));
            mx1 = fmaxf(mx1, fmaxf(s[nt][2], s[nt][3]));
        }
        mx0 = fmaxf(mx0, __shfl_xor_sync(0xffffffffu, mx0, 1));
        mx0 = fmaxf(mx0, __shfl_xor_sync(0xffffffffu, mx0, 2));
        mx1 = fmaxf(mx1, __shfl_xor_sync(0xffffffffu, mx1, 1));
        mx1 = fmaxf(mx1, __shfl_xor_sync(0xffffffffu, mx1, 2));

        float mn0 = fmaxf(m0, mx0), mn1 = fmaxf(m1, mx1);
        float a0 = __expf(m0 - mn0), a1 = __expf(m1 - mn1);
        m0 = mn0; m1 = mn1;

        float sum0 = 0.0f, sum1 = 0.0f;
#pragma unroll
        for (int nt = 0; nt < 8; nt++) {
            s[nt][0] = __expf(s[nt][0] - mn0);
            s[nt][1] = __expf(s[nt][1] - mn0);
            s[nt][2] = __expf(s[nt][2] - mn1);
            s[nt][3] = __expf(s[nt][3] - mn1);
            sum0 += s[nt][0] + s[nt][1];
            sum1 += s[nt][2] + s[nt][3];
        }
        sum0 += __shfl_xor_sync(0xffffffffu, sum0, 1);
        sum0 += __shfl_xor_sync(0xffffffffu, sum0, 2);
        sum1 += __shfl_xor_sync(0xffffffffu, sum1, 1);
        sum1 += __shfl_xor_sync(0xffffffffu, sum1, 2);
        l0 = l0 * a0 + sum0;
        l1 = l1 * a1 + sum1;

#pragma unroll
        for (int nt = 0; nt < 16; nt++) {
            o[nt][0] *= a0; o[nt][1] *= a0;
            o[nt][2] *= a1; o[nt][3] *= a1;
        }

        // ---- O += P V (P exact-split, V single)
#pragma unroll
        for (int kt = 0; kt < 4; kt++) {
            uint32_t pah[4], pal[4];
            {
                float e[8] = { s[2*kt][0], s[2*kt][1], s[2*kt][2], s[2*kt][3],
                               s[2*kt+1][0], s[2*kt+1][1], s[2*kt+1][2], s[2*kt+1][3] };
                float hf[8], lf[8];
#pragma unroll
                for (int q = 0; q < 8; q++) {
                    __half hb = __float2half(e[q]);
                    hf[q] = __half2float(hb);
                    lf[q] = e[q] - hf[q];
                }
                pah[0] = packh2(hf[0], hf[1]);
                pah[1] = packh2(hf[2], hf[3]);
                pah[2] = packh2(hf[4], hf[5]);
                pah[3] = packh2(hf[6], hf[7]);
                pal[0] = packh2(lf[0], lf[1]);
                pal[1] = packh2(lf[2], lf[3]);
                pal[2] = packh2(lf[4], lf[5]);
                pal[3] = packh2(lf[6], lf[7]);
            }
            const int j = lane >> 3, ll = lane & 7;
            const int rr = kt * 16 + (j & 1) * 8 + ll;
#pragma unroll
            for (int gn = 0; gn < 8; gn++) {
                uint32_t vf4[4];
                uint32_t off = swz256(rr, gn * 2 + (j >> 1));
                ldsm4t(vf4, bK + KVTILE_B + off);
#pragma unroll
                for (int sel = 0; sel < 2; sel++) {
                    int nt = gn * 2 + sel;
                    mma16816h(o[nt], pah, vf4[sel * 2], vf4[sel * 2 + 1]);
                    mma16816h(o[nt], pal, vf4[sel * 2], vf4[sel * 2 + 1]);
                }
            }
        }

        }  // end fully-masked skip

        if (++buf == 3) buf = 0;
    }

    // ---- finalize: write split AO (fp16 hi/lo)
    const float i0 = 1.0f / l0, i1 = 1.0f / l1;
#pragma unroll
    for (int nt = 0; nt < 16; nt++) {
        int col = h * HD + nt * 8 + (lane & 3) * 2;
        __half2 hh, ll2;
        split2h(o[nt][0] * i0, o[nt][1] * i0, &hh, &ll2);
        *(__half2*)(Ohi + (size_t)row0 * QDIM + col) = hh;
        *(__half2*)(Olo + (size_t)row0 * QDIM + col) = ll2;
        split2h(o[nt][2] * i1, o[nt][3] * i1, &hh, &ll2);
        *(__half2*)(Ohi + (size_t)row1 * QDIM + col) = hh;
        *(__half2*)(Olo + (size_t)row1 * QDIM + col) = ll2;
    }
}

// ---------------------------------------------------------------------------
extern "C" void kernel_launch(void* const* d_in, const int* in_sizes, int n_in,
                              void* d_out, int out_size)
{
    const float* hidden = (const float*)d_in[0];
    const float* cosb   = (const float*)d_in[1];
    const float* sinb   = (const float*)d_in[2];
    const float* Wq     = (const float*)d_in[3];
    const float* Wk     = (const float*)d_in[4];
    const float* Wv     = (const float*)d_in[5];
    const float* Wo     = (const float*)d_in[6];
    const float* qw     = (const float*)d_in[7];
    const float* kw     = (const float*)d_in[8];
    float* out = (float*)d_out;

    float *Qp, *Kp;
    cudaGetSymbolAddress((void**)&Qp,  g_Q);
    cudaGetSymbolAddress((void**)&Kp,  g_K);

    __half *Xh, *Xl, *Wqf, *Wkf, *Wvf, *Wof, *AOh, *AOl;
    __half *Qh2, *Ql2, *Kf2, *Vf2;
    cudaGetSymbolAddress((void**)&Xh,  g_Xh);   cudaGetSymbolAddress((void**)&Xl,  g_Xl);
    cudaGetSymbolAddress((void**)&Wqf, g_Wqf);
    cudaGetSymbolAddress((void**)&Wkf, g_Wkf);
    cudaGetSymbolAddress((void**)&Wvf, g_Wvf);
    cudaGetSymbolAddress((void**)&Wof, g_Wof);
    cudaGetSymbolAddress((void**)&AOh, g_AOh);  cudaGetSymbolAddress((void**)&AOl, g_AOl);
    cudaGetSymbolAddress((void**)&Qh2, g_Qh2);  cudaGetSymbolAddress((void**)&Ql2, g_Ql2);
    cudaGetSymbolAddress((void**)&Kf2, g_Kf2);
    cudaGetSymbolAddress((void**)&Vf2, g_Vf2);

    cudaFuncSetAttribute(gemm_q_cvtwo,
                         cudaFuncAttributeMaxDynamicSharedMemorySize, GSM_TOTAL);
    cudaFuncSetAttribute(gemm_o,
                         cudaFuncAttributeMaxDynamicSharedMemorySize, GSM_TOTAL);
    cudaFuncSetAttribute(gemm_kv,
                         cudaFuncAttributeMaxDynamicSharedMemorySize, GSM_TOTAL);
    cudaFuncSetAttribute(attn_mma,
                         cudaFuncAttributeMaxDynamicSharedMemorySize, ASM_TOTAL);

    // L0: conversions (X split; Wq/Wk/Wv single). Wo folded into L1.
    cvt_all<<<CVT_BLOCKS, 256>>>(hidden, Xh, Xl, Wq, Wqf, Wk, Wkf, Wv, Wvf);

    // L1: Q projection + Wo conversion
    gemm_q_cvtwo<<<dim3(QDIM / 128 + 16, SEQ / 128), GTHREADS, GSM_TOTAL>>>(
        Xh, Xl, Wqf, Qp, Wo, Wof);

    // L2: fused K+V projection
    gemm_kv<<<dim3(2 * KVDIM / 128, SEQ / 128), GTHREADS, GSM_TOTAL>>>(
        Xh, Xl, Wkf, Wvf, Kp, Vf2);

    // L3: RMSNorm + RoPE (Q -> split, K -> single)
    rms_both<<<RMS_BLOCKS, 256>>>(Qp, Kp, qw, kw, cosb, sinb, Qh2, Ql2, Kf2);

    // L4: flash attention -> split AO
    attn_mma<<<dim3(SEQ / 128, NH), 256, ASM_TOTAL>>>(
        Qh2, Ql2, Kf2, Vf2, AOh, AOl);

    // L5: output projection
    gemm_o<<<dim3(HID / 128, SEQ / 128), GTHREADS, GSM_TOTAL>>>(
        AOh, AOl, Wof, out);
}

// round 15
// speedup vs baseline: 2.6011x; 1.5978x over previous
#include <cuda_runtime.h>
#include <cuda_fp16.h>
#include <stdint.h>
#include <math.h>

// Problem constants (B=1)
#define SEQ   2048
#define HID   4096
#define NH    32
#define NKV   8
#define HD    128
#define QDIM  (NH * HD)   // 4096
#define KVDIM (NKV * HD)  // 1024
#define RSCALE 0.08838834764831845f  // 128^-0.5
#define REPS   1e-6f

// ---------------------------------------------------------------------------
// Scratch (__device__ globals: allocation-free rule)
// ---------------------------------------------------------------------------
__device__ float g_Q[SEQ * QDIM];
__device__ float g_K[SEQ * KVDIM];

__device__ __half g_Xf[SEQ * HID];
__device__ __half g_Wqf[QDIM * HID];
__device__ __half g_Wkf[KVDIM * HID];
__device__ __half g_Wvf[KVDIM * HID];
__device__ __half g_Wof[HID * QDIM];
__device__ __half g_AOf[SEQ * QDIM];

__device__ __half g_Qh2[SEQ * QDIM], g_Ql2[SEQ * QDIM];
__device__ __half g_Kf2[SEQ * KVDIM];
__device__ __half g_Vf2[SEQ * KVDIM];

// ---------------------------------------------------------------------------
// PTX helpers (base sm_100-safe)
// ---------------------------------------------------------------------------
__device__ __forceinline__ uint32_t smem_u32(const void* p) {
    uint32_t a;
    asm("{ .reg .u64 t; cvta.to.shared.u64 t, %1; cvt.u32.u64 %0, t; }"
        : "=r"(a) : "l"(p));
    return a;
}

__device__ __forceinline__ void ldsm4(uint32_t* r, uint32_t addr) {
    asm volatile("ldmatrix.sync.aligned.m8n8.x4.shared.b16 {%0,%1,%2,%3}, [%4];"
                 : "=r"(r[0]), "=r"(r[1]), "=r"(r[2]), "=r"(r[3]) : "r"(addr));
}

__device__ __forceinline__ void ldsm4t(uint32_t* r, uint32_t addr) {
    asm volatile("ldmatrix.sync.aligned.m8n8.x4.trans.shared.b16 {%0,%1,%2,%3}, [%4];"
                 : "=r"(r[0]), "=r"(r[1]), "=r"(r[2]), "=r"(r[3]) : "r"(addr));
}

// fp16 inputs, fp32 accumulate
__device__ __forceinline__ void mma16816h(float* c, const uint32_t* a,
                                          uint32_t b0, uint32_t b1) {
    asm volatile(
        "mma.sync.aligned.m16n8k16.row.col.f32.f16.f16.f32 "
        "{%0,%1,%2,%3}, {%4,%5,%6,%7}, {%8,%9}, {%0,%1,%2,%3};"
        : "+f"(c[0]), "+f"(c[1]), "+f"(c[2]), "+f"(c[3])
        : "r"(a[0]), "r"(a[1]), "r"(a[2]), "r"(a[3]), "r"(b0), "r"(b1));
}

__device__ __forceinline__ uint32_t packh2(float lo, float hi) {
    __half2 t = __floats2half2_rn(lo, hi);
    return *(uint32_t*)&t;
}

// fp32 -> fp16 hi + fp16 lo residual
__device__ __forceinline__ void split2h(float a, float b,
                                        __half2* h, __half2* l) {
    __half ha = __float2half(a);
    __half hb = __float2half(b);
    h->x = ha; h->y = hb;
    l->x = __float2half(a - __half2float(ha));
    l->y = __float2half(b - __half2float(hb));
}

// ---------------------------------------------------------------------------
// Fused conversions: X, Wq, Wk, Wv -> fp16 single.
//   X: [0, 8192)  Wq: [8192, 24576)  Wk: [24576, 28672)  Wv: [28672, 32768)
// ---------------------------------------------------------------------------
#define CVT_BLOCKS 32768

__global__ __launch_bounds__(256) void cvt_all(
    const float* __restrict__ x,  __half* __restrict__ xf,
    const float* __restrict__ wq, __half* __restrict__ wqf,
    const float* __restrict__ wk, __half* __restrict__ wkf,
    const float* __restrict__ wv, __half* __restrict__ wvf)
{
    const int b = blockIdx.x;
    const float* src;
    __half* dst;
    int base;
    if (b < 8192)       { src = x;  dst = xf;  base = 0; }
    else if (b < 24576) { src = wq; dst = wqf; base = 8192; }
    else if (b < 28672) { src = wk; dst = wkf; base = 24576; }
    else                { src = wv; dst = wvf; base = 28672; }
    const int i = ((b - base) * 256 + threadIdx.x) * 4;
    float4 v = *(const float4*)(src + i);
    *(__half2*)(dst + i)     = __floats2half2_rn(v.x, v.y);
    *(__half2*)(dst + i + 2) = __floats2half2_rn(v.z, v.w);
}

// ---------------------------------------------------------------------------
// mma.sync fp16 single-single GEMM core: C = Af[M,K] * Bf[N,K]^T, 1 pass.
// 512 threads, 128x128 CTA tile, BK=64, 3-stage cp.async pipeline.
// ---------------------------------------------------------------------------
#define GTHREADS 512
#define TILE_B   16384                 // 128 rows x 128B (64 fp16 cols)
#define GSTAGE_B (2 * TILE_B)          // Af, Bf
#define GSM_TOTAL (3 * GSTAGE_B)       // 98304

__device__ __forceinline__ void load_tile64(
    uint32_t sdst, const __half* __restrict__ g,
    int row0, int kc, int K, int tid)
{
#pragma unroll
    for (int s = 0; s < 2; s++) {
        int idx = tid + s * GTHREADS;
        int r = idx >> 3;
        int u = idx & 7;
        uint32_t sw = (uint32_t)(r * 128 + ((u ^ (r & 7)) << 4));
        const __half* gp = g + (size_t)(row0 + r) * K + kc * 64 + u * 8;
        asm volatile("cp.async.cg.shared.global [%0], [%1], 16;"
                     :: "r"(sdst + sw), "l"(gp) : "memory");
    }
}

__device__ __forceinline__ void gemm_core(
    const __half* __restrict__ Af, const __half* __restrict__ Bf,
    float* __restrict__ C, __half* __restrict__ Ch,
    int N, int K, int bm, int bn, char* smem)
{
    const uint32_t sb = smem_u32(smem);
    const int tid  = threadIdx.x;
    const int lane = tid & 31;
    const int warp = tid >> 5;
    const int wm = warp >> 2;
    const int wn = warp & 3;
    const int NC = K >> 6;

    float acc[2][4][4];
#pragma unroll
    for (int i = 0; i < 2; i++)
#pragma unroll
        for (int j = 0; j < 4; j++)
#pragma unroll
            for (int q = 0; q < 4; q++) acc[i][j][q] = 0.0f;

    // Prologue: stages 0 and 1
#pragma unroll
    for (int c = 0; c < 2; c++) {
        uint32_t b = sb + c * GSTAGE_B;
        load_tile64(b,          Af, bm, c, K, tid);
        load_tile64(b + TILE_B, Bf, bn, c, K, tid);
        asm volatile("cp.async.commit_group;" ::: "memory");
    }

    const int a_r  = wm * 32 + (lane & 15);
    const int a_ku = lane >> 4;
    const int b_r  = wn * 32 + ((lane >> 3) & 1) * 8 + (lane & 7);
    const int b_ku = lane >> 4;

    int buf = 0;
    for (int c = 0; c < NC; c++) {
        if (c + 1 < NC)
            asm volatile("cp.async.wait_group 1;" ::: "memory");
        else
            asm volatile("cp.async.wait_group 0;" ::: "memory");
        __syncthreads();

        if (c + 2 < NC) {
            int nb = buf + 2; if (nb >= 3) nb -= 3;
            uint32_t b2 = sb + nb * GSTAGE_B;
            load_tile64(b2,          Af, bm, c + 2, K, tid);
            load_tile64(b2 + TILE_B, Bf, bn, c + 2, K, tid);
            asm volatile("cp.async.commit_group;" ::: "memory");
        }

        const uint32_t b = sb + buf * GSTAGE_B;
        const uint32_t sAf = b;
        const uint32_t sBf = b + TILE_B;

#pragma unroll
        for (int ks = 0; ks < 4; ks++) {
            const int ku0 = ks * 2;
            uint32_t aF[2][4];
#pragma unroll
            for (int mt = 0; mt < 2; mt++) {
                int r = a_r + mt * 16;
                int ku = ku0 + a_ku;
                uint32_t off = (uint32_t)(r * 128 + ((ku ^ (r & 7)) << 4));
                ldsm4(aF[mt], sAf + off);
            }
            uint32_t bF[2][4];
#pragma unroll
            for (int ntp = 0; ntp < 2; ntp++) {
                int r = b_r + ntp * 16;
                int ku = ku0 + b_ku;
                uint32_t off = (uint32_t)(r * 128 + ((ku ^ (r & 7)) << 4));
                ldsm4(bF[ntp], sBf + off);
            }
#pragma unroll
            for (int mt = 0; mt < 2; mt++) {
#pragma unroll
                for (int nt = 0; nt < 4; nt++) {
                    const int ntp = nt >> 1;
                    const int sel = nt & 1;
                    mma16816h(acc[mt][nt], aF[mt], bF[ntp][sel], bF[ntp][sel + 2]);
                }
            }
        }
        if (++buf == 3) buf = 0;
    }

    // Epilogue: fp32 (C) or fp16-single (Ch)
#pragma unroll
    for (int mt = 0; mt < 2; mt++) {
        const int row = bm + wm * 32 + mt * 16 + (lane >> 2);
#pragma unroll
        for (int nt = 0; nt < 4; nt++) {
            const int col = bn + wn * 32 + nt * 8 + (lane & 3) * 2;
            if (C) {
                *(float2*)(C + (size_t)row * N + col) =
                    make_float2(acc[mt][nt][0], acc[mt][nt][1]);
                *(float2*)(C + (size_t)(row + 8) * N + col) =
                    make_float2(acc[mt][nt][2], acc[mt][nt][3]);
            } else {
                *(__half2*)(Ch + (size_t)row * N + col) =
                    __floats2half2_rn(acc[mt][nt][0], acc[mt][nt][1]);
                *(__half2*)(Ch + (size_t)(row + 8) * N + col) =
                    __floats2half2_rn(acc[mt][nt][2], acc[mt][nt][3]);
            }
        }
    }
}

// Q projection + folded Wo single-conversion.
__global__ __launch_bounds__(GTHREADS)
void gemm_q_cvtwo(const __half* __restrict__ Af, const __half* __restrict__ Bf,
                  float* __restrict__ C,
                  const float* __restrict__ wo, __half* __restrict__ wof)
{
    extern __shared__ __align__(1024) char smem[];
    if (blockIdx.x < QDIM / 128) {
        gemm_core(Af, Bf, C, nullptr, QDIM, HID,
                  blockIdx.y * 128, blockIdx.x * 128, smem);
    } else {
        const int sid = (blockIdx.x - QDIM / 128) * (int)gridDim.y + blockIdx.y;
        const size_t n_per = ((size_t)HID * QDIM) / 256;   // 65536
        const size_t base = (size_t)sid * n_per;
        for (size_t i = base + threadIdx.x * 4; i < base + n_per;
             i += (size_t)GTHREADS * 4) {
            float4 v = *(const float4*)(wo + i);
            *(__half2*)(wof + i)     = __floats2half2_rn(v.x, v.y);
            *(__half2*)(wof + i + 2) = __floats2half2_rn(v.z, v.w);
        }
    }
}

// O projection
__global__ __launch_bounds__(GTHREADS)
void gemm_o(const __half* __restrict__ Af, const __half* __restrict__ Bf,
            float* __restrict__ C)
{
    extern __shared__ __align__(1024) char smem[];
    gemm_core(Af, Bf, C, nullptr, HID, QDIM,
              blockIdx.y * 128, blockIdx.x * 128, smem);
}

// Fused K+V projection: bx < 8 -> K (fp32 out), else V (fp16 single out)
__global__ __launch_bounds__(GTHREADS)
void gemm_kv(const __half* __restrict__ Af,
             const __half* __restrict__ Bkf, const __half* __restrict__ Bvf,
             float* __restrict__ Ck, __half* __restrict__ Cvf)
{
    extern __shared__ __align__(1024) char smem[];
    const int bx = blockIdx.x;
    if (bx < KVDIM / 128) {
        gemm_core(Af, Bkf, Ck, nullptr, KVDIM, HID,
                  blockIdx.y * 128, bx * 128, smem);
    } else {
        gemm_core(Af, Bvf, nullptr, Cvf, KVDIM, HID,
                  blockIdx.y * 128, (bx - KVDIM / 128) * 128, smem);
    }
}

// ---------------------------------------------------------------------------
// Fused RMSNorm + RoPE. Q -> fp16 split (qh, ql); K -> fp16 single (kf).
// ---------------------------------------------------------------------------
#define RMS_BLOCKS (8192 + 2048)

__global__ __launch_bounds__(256) void rms_both(
    const float* __restrict__ Qf, const float* __restrict__ Kf,
    const float* __restrict__ qw, const float* __restrict__ kw,
    const float* __restrict__ cosb, const float* __restrict__ sinb,
    __half* __restrict__ qh, __half* __restrict__ ql,
    __half* __restrict__ kf)
{
    const int b = blockIdx.x;
    const float* X;
    const float* w;
    int nheads, row;
    bool isq;
    if (b < 8192) { X = Qf; w = qw; nheads = NH;  row = b * 8; isq = true; }
    else          { X = Kf; w = kw; nheads = NKV; row = (b - 8192) * 8; isq = false; }
    row += threadIdx.x >> 5;
    const int lane = threadIdx.x & 31;
    const int s = row / nheads;

    const float* x = X + (size_t)row * HD;
    float4 v = *(const float4*)(x + lane * 4);

    float ss = v.x * v.x + v.y * v.y + v.z * v.z + v.w * v.w;
#pragma unroll
    for (int o = 16; o > 0; o >>= 1) ss += __shfl_xor_sync(0xffffffffu, ss, o);
    const float inv = rsqrtf(ss * (1.0f / 128.0f) + REPS);

    float4 wv = *(const float4*)(w + lane * 4);
    float x0 = v.x * inv * wv.x;
    float x1 = v.y * inv * wv.y;
    float x2 = v.z * inv * wv.z;
    float x3 = v.w * inv * wv.w;

    float p0 = __shfl_xor_sync(0xffffffffu, x0, 16);
    float p1 = __shfl_xor_sync(0xffffffffu, x1, 16);
    float p2 = __shfl_xor_sync(0xffffffffu, x2, 16);
    float p3 = __shfl_xor_sync(0xffffffffu, x3, 16);
    const float sgn = (lane < 16) ? -1.0f : 1.0f;

    const float* cp = cosb + (size_t)s * HD + lane * 4;
    const float* sp = sinb + (size_t)s * HD + lane * 4;
    float4 c = *(const float4*)cp;
    float4 sn = *(const float4*)sp;

    float o0 = x0 * c.x + sgn * p0 * sn.x;
    float o1 = x1 * c.y + sgn * p1 * sn.y;
    float o2 = x2 * c.z + sgn * p2 * sn.z;
    float o3 = x3 * c.w + sgn * p3 * sn.w;

    size_t base = (size_t)row * HD + lane * 4;
    if (isq) {
        __half2 h, l;
        split2h(o0, o1, &h, &l);
        *(__half2*)(qh + base)     = h;
        *(__half2*)(ql + base)     = l;
        split2h(o2, o3, &h, &l);
        *(__half2*)(qh + base + 2) = h;
        *(__half2*)(ql + base + 2) = l;
    } else {
        *(__half2*)(kf + base)     = __floats2half2_rn(o0, o1);
        *(__half2*)(kf + base + 2) = __floats2half2_rn(o2, o3);
    }
}

// ---------------------------------------------------------------------------
// Tensor-core flash attention (fp16), causal, GQA, 3-stage pipeline,
// warp-level skip of fully-masked blocks. Q split (exact), K/V single fp16,
// P split (exact). Writes AO as fp16 single.
// ---------------------------------------------------------------------------
#define KVTILE_B 16384                    // 64 rows x 256B
#define ASTAGE_B (2 * KVTILE_B)           // Kf, Vf
#define ASM_TOTAL (3 * ASTAGE_B)          // 98304

__device__ __forceinline__ uint32_t swz256(int r, int u) {
    return (uint32_t)(r * 256 + ((u ^ (r & 7)) << 4));
}

__device__ __forceinline__ void attn_load_kv(
    uint32_t base, const __half* __restrict__ Kf,
    const __half* __restrict__ Vf, int k0, int kvh, int tid)
{
#pragma unroll
    for (int t = 0; t < 4; t++) {
        int idx = tid + t * 256;
        int r = idx >> 4, u = idx & 15;
        size_t go = (size_t)(k0 + r) * KVDIM + kvh * HD + u * 8;
        uint32_t sw = swz256(r, u);
        asm volatile("cp.async.cg.shared.global [%0], [%1], 16;"
                     :: "r"(base + sw), "l"(Kf + go) : "memory");
        asm volatile("cp.async.cg.shared.global [%0], [%1], 16;"
                     :: "r"(base + KVTILE_B + sw), "l"(Vf + go) : "memory");
    }
}

__global__ __launch_bounds__(256, 1)
void attn_mma(const __half* __restrict__ Qh, const __half* __restrict__ Ql,
              const __half* __restrict__ Kf, const __half* __restrict__ Vf,
              __half* __restrict__ Of)
{
    extern __shared__ __align__(1024) char smem[];
    const uint32_t sb = smem_u32(smem);
    const int tid  = threadIdx.x;
    const int lane = tid & 31;
    const int warp = tid >> 5;
    const int qb = (int)gridDim.x - 1 - (int)blockIdx.x;
    const int h  = blockIdx.y;
    const int kvh = h >> 2;
    const int q0 = qb * 128;
    const int NB = 2 * qb + 2;

    // ---- Stage Q through smem, build register fragments (hi then lo)
    uint32_t qfh[8][4], qfl[8][4];
#pragma unroll
    for (int comp = 0; comp < 2; comp++) {
        const __half* src = comp ? Ql : Qh;
        for (int t = 0; t < 8; t++) {
            int idx = tid + t * 256;
            int r = idx >> 4, u = idx & 15;
            const __half* gp = src + (size_t)(q0 + r) * QDIM + h * HD + u * 8;
            asm volatile("cp.async.cg.shared.global [%0], [%1], 16;"
                         :: "r"(sb + swz256(r, u)), "l"(gp) : "memory");
        }
        asm volatile("cp.async.commit_group;" ::: "memory");
        asm volatile("cp.async.wait_group 0;" ::: "memory");
        __syncthreads();
        {
            int r = warp * 16 + (lane & 15);
#pragma unroll
            for (int ks = 0; ks < 8; ks++) {
                uint32_t addr = sb + swz256(r, 2 * ks + (lane >> 4));
                if (comp) ldsm4(qfl[ks], addr);
                else      ldsm4(qfh[ks], addr);
            }
        }
        __syncthreads();
    }

    float o[16][4];
#pragma unroll
    for (int i = 0; i < 16; i++)
#pragma unroll
        for (int q = 0; q < 4; q++) o[i][q] = 0.0f;
    float m0 = -1e30f, m1 = -1e30f, l0 = 0.0f, l1 = 0.0f;

    const int row0 = q0 + warp * 16 + (lane >> 2);
    const int row1 = row0 + 8;
    const int row_top = q0 + warp * 16 + 15;

    // ---- prologue: stages 0 and 1
    attn_load_kv(sb, Kf, Vf, 0, kvh, tid);
    asm volatile("cp.async.commit_group;" ::: "memory");
    if (NB > 1) {
        attn_load_kv(sb + ASTAGE_B, Kf, Vf, 64, kvh, tid);
        asm volatile("cp.async.commit_group;" ::: "memory");
    }

    int buf = 0;
    for (int kb = 0; kb < NB; kb++) {
        if (kb + 1 < NB)
            asm volatile("cp.async.wait_group 1;" ::: "memory");
        else
            asm volatile("cp.async.wait_group 0;" ::: "memory");
        __syncthreads();

        if (kb + 2 < NB) {
            int nb = buf + 2; if (nb >= 3) nb -= 3;
            attn_load_kv(sb + nb * ASTAGE_B, Kf, Vf, (kb + 2) * 64, kvh, tid);
            asm volatile("cp.async.commit_group;" ::: "memory");
        }

        const uint32_t bK = sb + buf * ASTAGE_B;
        const int k0 = kb * 64;

        if (k0 <= row_top) {   // skip fully-masked blocks (exact)

        // ---- S = Q K^T (fp16, Q exact-split)
        float s[8][4];
#pragma unroll
        for (int nt = 0; nt < 8; nt++)
#pragma unroll
            for (int q = 0; q < 4; q++) s[nt][q] = 0.0f;

#pragma unroll
        for (int ks = 0; ks < 8; ks++) {
#pragma unroll
            for (int g = 0; g < 4; g++) {
                uint32_t kf4[4];
                int rr = g * 16 + ((lane >> 3) & 1) * 8 + (lane & 7);
                uint32_t off = swz256(rr, 2 * ks + (lane >> 4));
                ldsm4(kf4, bK + off);
#pragma unroll
                for (int sel = 0; sel < 2; sel++) {
                    int nt = g * 2 + sel;
                    mma16816h(s[nt], qfh[ks], kf4[sel], kf4[sel + 2]);
                    mma16816h(s[nt], qfl[ks], kf4[sel], kf4[sel + 2]);
                }
            }
        }

        // ---- scale + causal mask
        const bool domask = (k0 + 63) > row0;
#pragma unroll
        for (int nt = 0; nt < 8; nt++) {
            int c0 = k0 + nt * 8 + (lane & 3) * 2;
#pragma unroll
            for (int q = 0; q < 4; q++) s[nt][q] *= RSCALE;
            if (domask) {
                if (c0     > row0) s[nt][0] = -1e30f;
                if (c0 + 1 > row0) s[nt][1] = -1e30f;
                if (c0     > row1) s[nt][2] = -1e30f;
                if (c0 + 1 > row1) s[nt][3] = -1e30f;
            }
        }

        // ---- online softmax
        float mx0 = -1e30f, mx1 = -1e30f;
#pragma unroll
        for (int nt = 0; nt < 8; nt++) {
            mx0 = fmaxf(mx0, fmaxf(s[nt][0], s[nt][1]));
            mx1 = fmaxf(mx1, fmaxf(s[nt][2], s[nt][3]));
        }
        mx0 = fmaxf(mx0, __shfl_xor_sync(0xffffffffu, mx0, 1));
        mx0 = fmaxf(mx0, __shfl_xor_sync(0xffffffffu, mx0, 2));
        mx1 = fmaxf(mx1, __shfl_xor_sync(0xffffffffu, mx1, 1));
        mx1 = fmaxf(mx1, __shfl_xor_sync(0xffffffffu, mx1, 2));

        float mn0 = fmaxf(m0, mx0), mn1 = fmaxf(m1, mx1);
        float a0 = __expf(m0 - mn0), a1 = __expf(m1 - mn1);
        m0 = mn0; m1 = mn1;

        float sum0 = 0.0f, sum1 = 0.0f;
#pragma unroll
        for (int nt = 0; nt < 8; nt++) {
            s[nt][0] = __expf(s[nt][0] - mn0);
            s[nt][1] = __expf(s[nt][1] - mn0);
            s[nt][2] = __expf(s[nt][2] - mn1);
            s[nt][3] = __expf(s[nt][3] - mn1);
            sum0 += s[nt][0] + s[nt][1];
            sum1 += s[nt][2] + s[nt][3];
        }
        sum0 += __shfl_xor_sync(0xffffffffu, sum0, 1);
        sum0 += __shfl_xor_sync(0xffffffffu, sum0, 2);
        sum1 += __shfl_xor_sync(0xffffffffu, sum1, 1);
        sum1 += __shfl_xor_sync(0xffffffffu, sum1, 2);
        l0 = l0 * a0 + sum0;
        l1 = l1 * a1 + sum1;

#pragma unroll
        for (int nt = 0; nt < 16; nt++) {
            o[nt][0] *= a0; o[nt][1] *= a0;
            o[nt][2] *= a1; o[nt][3] *= a1;
        }

        // ---- O += P V (P exact-split, V single)
#pragma unroll
        for (int kt = 0; kt < 4; kt++) {
            uint32_t pah[4], pal[4];
            {
                float e[8] = { s[2*kt][0], s[2*kt][1], s[2*kt][2], s[2*kt][3],
                               s[2*kt+1][0], s[2*kt+1][1], s[2*kt+1][2], s[2*kt+1][3] };
                float hf[8], lf[8];
#pragma unroll
                for (int q = 0; q < 8; q++) {
                    __half hb = __float2half(e[q]);
                    hf[q] = __half2float(hb);
                    lf[q] = e[q] - hf[q];
                }
                pah[0] = packh2(hf[0], hf[1]);
                pah[1] = packh2(hf[2], hf[3]);
                pah[2] = packh2(hf[4], hf[5]);
                pah[3] = packh2(hf[6], hf[7]);
                pal[0] = packh2(lf[0], lf[1]);
                pal[1] = packh2(lf[2], lf[3]);
                pal[2] = packh2(lf[4], lf[5]);
                pal[3] = packh2(lf[6], lf[7]);
            }
            const int j = lane >> 3, ll = lane & 7;
            const int rr = kt * 16 + (j & 1) * 8 + ll;
#pragma unroll
            for (int gn = 0; gn < 8; gn++) {
                uint32_t vf4[4];
                uint32_t off = swz256(rr, gn * 2 + (j >> 1));
                ldsm4t(vf4, bK + KVTILE_B + off);
#pragma unroll
                for (int sel = 0; sel < 2; sel++) {
                    int nt = gn * 2 + sel;
                    mma16816h(o[nt], pah, vf4[sel * 2], vf4[sel * 2 + 1]);
                    mma16816h(o[nt], pal, vf4[sel * 2], vf4[sel * 2 + 1]);
                }
            }
        }

        }  // end fully-masked skip

        if (++buf == 3) buf = 0;
    }

    // ---- finalize: write AO as fp16 single
    const float i0 = 1.0f / l0, i1 = 1.0f / l1;
#pragma unroll
    for (int nt = 0; nt < 16; nt++) {
        int col = h * HD + nt * 8 + (lane & 3) * 2;
        *(__half2*)(Of + (size_t)row0 * QDIM + col) =
            __floats2half2_rn(o[nt][0] * i0, o[nt][1] * i0);
        *(__half2*)(Of + (size_t)row1 * QDIM + col) =
            __floats2half2_rn(o[nt][2] * i1, o[nt][3] * i1);
    }
}

// ---------------------------------------------------------------------------
extern "C" void kernel_launch(void* const* d_in, const int* in_sizes, int n_in,
                              void* d_out, int out_size)
{
    const float* hidden = (const float*)d_in[0];
    const float* cosb   = (const float*)d_in[1];
    const float* sinb   = (const float*)d_in[2];
    const float* Wq     = (const float*)d_in[3];
    const float* Wk     = (const float*)d_in[4];
    const float* Wv     = (const float*)d_in[5];
    const float* Wo     = (const float*)d_in[6];
    const float* qw     = (const float*)d_in[7];
    const float* kw     = (const float*)d_in[8];
    float* out = (float*)d_out;

    float *Qp, *Kp;
    cudaGetSymbolAddress((void**)&Qp,  g_Q);
    cudaGetSymbolAddress((void**)&Kp,  g_K);

    __half *Xf, *Wqf, *Wkf, *Wvf, *Wof, *AOf;
    __half *Qh2, *Ql2, *Kf2, *Vf2;
    cudaGetSymbolAddress((void**)&Xf,  g_Xf);
    cudaGetSymbolAddress((void**)&Wqf, g_Wqf);
    cudaGetSymbolAddress((void**)&Wkf, g_Wkf);
    cudaGetSymbolAddress((void**)&Wvf, g_Wvf);
    cudaGetSymbolAddress((void**)&Wof, g_Wof);
    cudaGetSymbolAddress((void**)&AOf, g_AOf);
    cudaGetSymbolAddress((void**)&Qh2, g_Qh2);  cudaGetSymbolAddress((void**)&Ql2, g_Ql2);
    cudaGetSymbolAddress((void**)&Kf2, g_Kf2);
    cudaGetSymbolAddress((void**)&Vf2, g_Vf2);

    cudaFuncSetAttribute(gemm_q_cvtwo,
                         cudaFuncAttributeMaxDynamicSharedMemorySize, GSM_TOTAL);
    cudaFuncSetAttribute(gemm_o,
                         cudaFuncAttributeMaxDynamicSharedMemorySize, GSM_TOTAL);
    cudaFuncSetAttribute(gemm_kv,
                         cudaFuncAttributeMaxDynamicSharedMemorySize, GSM_TOTAL);
    cudaFuncSetAttribute(attn_mma,
                         cudaFuncAttributeMaxDynamicSharedMemorySize, ASM_TOTAL);

    // L0: conversions (all single fp16). Wo folded into L1.
    cvt_all<<<CVT_BLOCKS, 256>>>(hidden, Xf, Wq, Wqf, Wk, Wkf, Wv, Wvf);

    // L1: Q projection + Wo conversion
    gemm_q_cvtwo<<<dim3(QDIM / 128 + 16, SEQ / 128), GTHREADS, GSM_TOTAL>>>(
        Xf, Wqf, Qp, Wo, Wof);

    // L2: fused K+V projection
    gemm_kv<<<dim3(2 * KVDIM / 128, SEQ / 128), GTHREADS, GSM_TOTAL>>>(
        Xf, Wkf, Wvf, Kp, Vf2);

    // L3: RMSNorm + RoPE (Q -> split, K -> single)
    rms_both<<<RMS_BLOCKS, 256>>>(Qp, Kp, qw, kw, cosb, sinb, Qh2, Ql2, Kf2);

    // L4: flash attention -> fp16 AO
    attn_mma<<<dim3(SEQ / 128, NH), 256, ASM_TOTAL>>>(
        Qh2, Ql2, Kf2, Vf2, AOf);

    // L5: output projection
    gemm_o<<<dim3(HID / 128, SEQ / 128), GTHREADS, GSM_TOTAL>>>(
        AOf, Wof, out);
}

// round 16
// speedup vs baseline: 2.9150x; 1.1207x over previous
#include <cuda_runtime.h>
#include <cuda_fp16.h>
#include <stdint.h>
#include <math.h>

// Problem constants (B=1)
#define SEQ   2048
#define HID   4096
#define NH    32
#define NKV   8
#define HD    128
#define QDIM  (NH * HD)   // 4096
#define KVDIM (NKV * HD)  // 1024
#define RSCALE 0.08838834764831845f  // 128^-0.5
#define REPS   1e-6f

// ---------------------------------------------------------------------------
// Scratch (__device__ globals: allocation-free rule)
// ---------------------------------------------------------------------------
__device__ float g_Q[SEQ * QDIM];
__device__ float g_K[SEQ * KVDIM];

__device__ __half g_Xf[SEQ * HID];
__device__ __half g_Wqf[QDIM * HID];
__device__ __half g_Wkf[KVDIM * HID];
__device__ __half g_Wvf[KVDIM * HID];
__device__ __half g_Wof[HID * QDIM];
__device__ __half g_AOf[SEQ * QDIM];

__device__ __half g_Qf2[SEQ * QDIM];
__device__ __half g_Kf2[SEQ * KVDIM];
__device__ __half g_Vf2[SEQ * KVDIM];

// ---------------------------------------------------------------------------
// PTX helpers (base sm_100-safe)
// ---------------------------------------------------------------------------
__device__ __forceinline__ uint32_t smem_u32(const void* p) {
    uint32_t a;
    asm("{ .reg .u64 t; cvta.to.shared.u64 t, %1; cvt.u32.u64 %0, t; }"
        : "=r"(a) : "l"(p));
    return a;
}

__device__ __forceinline__ void ldsm4(uint32_t* r, uint32_t addr) {
    asm volatile("ldmatrix.sync.aligned.m8n8.x4.shared.b16 {%0,%1,%2,%3}, [%4];"
                 : "=r"(r[0]), "=r"(r[1]), "=r"(r[2]), "=r"(r[3]) : "r"(addr));
}

__device__ __forceinline__ void ldsm4t(uint32_t* r, uint32_t addr) {
    asm volatile("ldmatrix.sync.aligned.m8n8.x4.trans.shared.b16 {%0,%1,%2,%3}, [%4];"
                 : "=r"(r[0]), "=r"(r[1]), "=r"(r[2]), "=r"(r[3]) : "r"(addr));
}

// fp16 inputs, fp32 accumulate
__device__ __forceinline__ void mma16816h(float* c, const uint32_t* a,
                                          uint32_t b0, uint32_t b1) {
    asm volatile(
        "mma.sync.aligned.m16n8k16.row.col.f32.f16.f16.f32 "
        "{%0,%1,%2,%3}, {%4,%5,%6,%7}, {%8,%9}, {%0,%1,%2,%3};"
        : "+f"(c[0]), "+f"(c[1]), "+f"(c[2]), "+f"(c[3])
        : "r"(a[0]), "r"(a[1]), "r"(a[2]), "r"(a[3]), "r"(b0), "r"(b1));
}

__device__ __forceinline__ uint32_t packh2(float lo, float hi) {
    __half2 t = __floats2half2_rn(lo, hi);
    return *(uint32_t*)&t;
}

// ---------------------------------------------------------------------------
// Fused conversions: X, Wq, Wk, Wv -> fp16 single.
//   X: [0, 8192)  Wq: [8192, 24576)  Wk: [24576, 28672)  Wv: [28672, 32768)
// ---------------------------------------------------------------------------
#define CVT_BLOCKS 32768

__global__ __launch_bounds__(256) void cvt_all(
    const float* __restrict__ x,  __half* __restrict__ xf,
    const float* __restrict__ wq, __half* __restrict__ wqf,
    const float* __restrict__ wk, __half* __restrict__ wkf,
    const float* __restrict__ wv, __half* __restrict__ wvf)
{
    const int b = blockIdx.x;
    const float* src;
    __half* dst;
    int base;
    if (b < 8192)       { src = x;  dst = xf;  base = 0; }
    else if (b < 24576) { src = wq; dst = wqf; base = 8192; }
    else if (b < 28672) { src = wk; dst = wkf; base = 24576; }
    else                { src = wv; dst = wvf; base = 28672; }
    const int i = ((b - base) * 256 + threadIdx.x) * 4;
    float4 v = *(const float4*)(src + i);
    *(__half2*)(dst + i)     = __floats2half2_rn(v.x, v.y);
    *(__half2*)(dst + i + 2) = __floats2half2_rn(v.z, v.w);
}

// ---------------------------------------------------------------------------
// mma.sync fp16 single-single GEMM core: C = Af[M,K] * Bf[N,K]^T, 1 pass.
// 512 threads, 128x128 CTA tile, BK=64, 3-stage cp.async pipeline.
// ---------------------------------------------------------------------------
#define GTHREADS 512
#define TILE_B   16384                 // 128 rows x 128B (64 fp16 cols)
#define GSTAGE_B (2 * TILE_B)          // Af, Bf
#define GSM_TOTAL (3 * GSTAGE_B)       // 98304

__device__ __forceinline__ void load_tile64(
    uint32_t sdst, const __half* __restrict__ g,
    int row0, int kc, int K, int tid)
{
#pragma unroll
    for (int s = 0; s < 2; s++) {
        int idx = tid + s * GTHREADS;
        int r = idx >> 3;
        int u = idx & 7;
        uint32_t sw = (uint32_t)(r * 128 + ((u ^ (r & 7)) << 4));
        const __half* gp = g + (size_t)(row0 + r) * K + kc * 64 + u * 8;
        asm volatile("cp.async.cg.shared.global [%0], [%1], 16;"
                     :: "r"(sdst + sw), "l"(gp) : "memory");
    }
}

__device__ __forceinline__ void gemm_core(
    const __half* __restrict__ Af, const __half* __restrict__ Bf,
    float* __restrict__ C, __half* __restrict__ Ch,
    int N, int K, int bm, int bn, char* smem)
{
    const uint32_t sb = smem_u32(smem);
    const int tid  = threadIdx.x;
    const int lane = tid & 31;
    const int warp = tid >> 5;
    const int wm = warp >> 2;
    const int wn = warp & 3;
    const int NC = K >> 6;

    float acc[2][4][4];
#pragma unroll
    for (int i = 0; i < 2; i++)
#pragma unroll
        for (int j = 0; j < 4; j++)
#pragma unroll
            for (int q = 0; q < 4; q++) acc[i][j][q] = 0.0f;

    // Prologue: stages 0 and 1
#pragma unroll
    for (int c = 0; c < 2; c++) {
        uint32_t b = sb + c * GSTAGE_B;
        load_tile64(b,          Af, bm, c, K, tid);
        load_tile64(b + TILE_B, Bf, bn, c, K, tid);
        asm volatile("cp.async.commit_group;" ::: "memory");
    }

    const int a_r  = wm * 32 + (lane & 15);
    const int a_ku = lane >> 4;
    const int b_r  = wn * 32 + ((lane >> 3) & 1) * 8 + (lane & 7);
    const int b_ku = lane >> 4;

    int buf = 0;
    for (int c = 0; c < NC; c++) {
        if (c + 1 < NC)
            asm volatile("cp.async.wait_group 1;" ::: "memory");
        else
            asm volatile("cp.async.wait_group 0;" ::: "memory");
        __syncthreads();

        if (c + 2 < NC) {
            int nb = buf + 2; if (nb >= 3) nb -= 3;
            uint32_t b2 = sb + nb * GSTAGE_B;
            load_tile64(b2,          Af, bm, c + 2, K, tid);
            load_tile64(b2 + TILE_B, Bf, bn, c + 2, K, tid);
            asm volatile("cp.async.commit_group;" ::: "memory");
        }

        const uint32_t b = sb + buf * GSTAGE_B;
        const uint32_t sAf = b;
        const uint32_t sBf = b + TILE_B;

#pragma unroll
        for (int ks = 0; ks < 4; ks++) {
            const int ku0 = ks * 2;
            uint32_t aF[2][4];
#pragma unroll
            for (int mt = 0; mt < 2; mt++) {
                int r = a_r + mt * 16;
                int ku = ku0 + a_ku;
                uint32_t off = (uint32_t)(r * 128 + ((ku ^ (r & 7)) << 4));
                ldsm4(aF[mt], sAf + off);
            }
            uint32_t bF[2][4];
#pragma unroll
            for (int ntp = 0; ntp < 2; ntp++) {
                int r = b_r + ntp * 16;
                int ku = ku0 + b_ku;
                uint32_t off = (uint32_t)(r * 128 + ((ku ^ (r & 7)) << 4));
                ldsm4(bF[ntp], sBf + off);
            }
#pragma unroll
            for (int mt = 0; mt < 2; mt++) {
#pragma unroll
                for (int nt = 0; nt < 4; nt++) {
                    const int ntp = nt >> 1;
                    const int sel = nt & 1;
                    mma16816h(acc[mt][nt], aF[mt], bF[ntp][sel], bF[ntp][sel + 2]);
                }
            }
        }
        if (++buf == 3) buf = 0;
    }

    // Epilogue: fp32 (C) or fp16-single (Ch)
#pragma unroll
    for (int mt = 0; mt < 2; mt++) {
        const int row = bm + wm * 32 + mt * 16 + (lane >> 2);
#pragma unroll
        for (int nt = 0; nt < 4; nt++) {
            const int col = bn + wn * 32 + nt * 8 + (lane & 3) * 2;
            if (C) {
                *(float2*)(C + (size_t)row * N + col) =
                    make_float2(acc[mt][nt][0], acc[mt][nt][1]);
                *(float2*)(C + (size_t)(row + 8) * N + col) =
                    make_float2(acc[mt][nt][2], acc[mt][nt][3]);
            } else {
                *(__half2*)(Ch + (size_t)row * N + col) =
                    __floats2half2_rn(acc[mt][nt][0], acc[mt][nt][1]);
                *(__half2*)(Ch + (size_t)(row + 8) * N + col) =
                    __floats2half2_rn(acc[mt][nt][2], acc[mt][nt][3]);
            }
        }
    }
}

// Q projection + folded Wo single-conversion.
__global__ __launch_bounds__(GTHREADS)
void gemm_q_cvtwo(const __half* __restrict__ Af, const __half* __restrict__ Bf,
                  float* __restrict__ C,
                  const float* __restrict__ wo, __half* __restrict__ wof)
{
    extern __shared__ __align__(1024) char smem[];
    if (blockIdx.x < QDIM / 128) {
        gemm_core(Af, Bf, C, nullptr, QDIM, HID,
                  blockIdx.y * 128, blockIdx.x * 128, smem);
    } else {
        const int sid = (blockIdx.x - QDIM / 128) * (int)gridDim.y + blockIdx.y;
        const size_t n_per = ((size_t)HID * QDIM) / 256;   // 65536
        const size_t base = (size_t)sid * n_per;
        for (size_t i = base + threadIdx.x * 4; i < base + n_per;
             i += (size_t)GTHREADS * 4) {
            float4 v = *(const float4*)(wo + i);
            *(__half2*)(wof + i)     = __floats2half2_rn(v.x, v.y);
            *(__half2*)(wof + i + 2) = __floats2half2_rn(v.z, v.w);
        }
    }
}

// O projection
__global__ __launch_bounds__(GTHREADS)
void gemm_o(const __half* __restrict__ Af, const __half* __restrict__ Bf,
            float* __restrict__ C)
{
    extern __shared__ __align__(1024) char smem[];
    gemm_core(Af, Bf, C, nullptr, HID, QDIM,
              blockIdx.y * 128, blockIdx.x * 128, smem);
}

// Fused K+V projection: bx < 8 -> K (fp32 out), else V (fp16 single out)
__global__ __launch_bounds__(GTHREADS)
void gemm_kv(const __half* __restrict__ Af,
             const __half* __restrict__ Bkf, const __half* __restrict__ Bvf,
             float* __restrict__ Ck, __half* __restrict__ Cvf)
{
    extern __shared__ __align__(1024) char smem[];
    const int bx = blockIdx.x;
    if (bx < KVDIM / 128) {
        gemm_core(Af, Bkf, Ck, nullptr, KVDIM, HID,
                  blockIdx.y * 128, bx * 128, smem);
    } else {
        gemm_core(Af, Bvf, nullptr, Cvf, KVDIM, HID,
                  blockIdx.y * 128, (bx - KVDIM / 128) * 128, smem);
    }
}

// ---------------------------------------------------------------------------
// Fused RMSNorm + RoPE. Q and K -> fp16 single.
// ---------------------------------------------------------------------------
#define RMS_BLOCKS (8192 + 2048)

__global__ __launch_bounds__(256) void rms_both(
    const float* __restrict__ Qf, const float* __restrict__ Kf,
    const float* __restrict__ qw, const float* __restrict__ kw,
    const float* __restrict__ cosb, const float* __restrict__ sinb,
    __half* __restrict__ qf, __half* __restrict__ kf)
{
    const int b = blockIdx.x;
    const float* X;
    const float* w;
    __half* dst;
    int nheads, row;
    if (b < 8192) { X = Qf; w = qw; dst = qf; nheads = NH;  row = b * 8; }
    else          { X = Kf; w = kw; dst = kf; nheads = NKV; row = (b - 8192) * 8; }
    row += threadIdx.x >> 5;
    const int lane = threadIdx.x & 31;
    const int s = row / nheads;

    const float* x = X + (size_t)row * HD;
    float4 v = *(const float4*)(x + lane * 4);

    float ss = v.x * v.x + v.y * v.y + v.z * v.z + v.w * v.w;
#pragma unroll
    for (int o = 16; o > 0; o >>= 1) ss += __shfl_xor_sync(0xffffffffu, ss, o);
    const float inv = rsqrtf(ss * (1.0f / 128.0f) + REPS);

    float4 wv = *(const float4*)(w + lane * 4);
    float x0 = v.x * inv * wv.x;
    float x1 = v.y * inv * wv.y;
    float x2 = v.z * inv * wv.z;
    float x3 = v.w * inv * wv.w;

    float p0 = __shfl_xor_sync(0xffffffffu, x0, 16);
    float p1 = __shfl_xor_sync(0xffffffffu, x1, 16);
    float p2 = __shfl_xor_sync(0xffffffffu, x2, 16);
    float p3 = __shfl_xor_sync(0xffffffffu, x3, 16);
    const float sgn = (lane < 16) ? -1.0f : 1.0f;

    const float* cp = cosb + (size_t)s * HD + lane * 4;
    const float* sp = sinb + (size_t)s * HD + lane * 4;
    float4 c = *(const float4*)cp;
    float4 sn = *(const float4*)sp;

    float o0 = x0 * c.x + sgn * p0 * sn.x;
    float o1 = x1 * c.y + sgn * p1 * sn.y;
    float o2 = x2 * c.z + sgn * p2 * sn.z;
    float o3 = x3 * c.w + sgn * p3 * sn.w;

    size_t base = (size_t)row * HD + lane * 4;
    *(__half2*)(dst + base)     = __floats2half2_rn(o0, o1);
    *(__half2*)(dst + base + 2) = __floats2half2_rn(o2, o3);
}

// ---------------------------------------------------------------------------
// Tensor-core flash attention (fp16 single everywhere), causal, GQA,
// 3-stage pipeline, warp-level skip of fully-masked blocks.
// Writes AO as fp16 single.
// ---------------------------------------------------------------------------
#define KVTILE_B 16384                    // 64 rows x 256B
#define ASTAGE_B (2 * KVTILE_B)           // Kf, Vf
#define ASM_TOTAL (3 * ASTAGE_B)          // 98304

__device__ __forceinline__ uint32_t swz256(int r, int u) {
    return (uint32_t)(r * 256 + ((u ^ (r & 7)) << 4));
}

__device__ __forceinline__ void attn_load_kv(
    uint32_t base, const __half* __restrict__ Kf,
    const __half* __restrict__ Vf, int k0, int kvh, int tid)
{
#pragma unroll
    for (int t = 0; t < 4; t++) {
        int idx = tid + t * 256;
        int r = idx >> 4, u = idx & 15;
        size_t go = (size_t)(k0 + r) * KVDIM + kvh * HD + u * 8;
        uint32_t sw = swz256(r, u);
        asm volatile("cp.async.cg.shared.global [%0], [%1], 16;"
                     :: "r"(base + sw), "l"(Kf + go) : "memory");
        asm volatile("cp.async.cg.shared.global [%0], [%1], 16;"
                     :: "r"(base + KVTILE_B + sw), "l"(Vf + go) : "memory");
    }
}

__global__ __launch_bounds__(256, 1)
void attn_mma(const __half* __restrict__ Qf, const __half* __restrict__ Kf,
              const __half* __restrict__ Vf, __half* __restrict__ Of)
{
    extern __shared__ __align__(1024) char smem[];
    const uint32_t sb = smem_u32(smem);
    const int tid  = threadIdx.x;
    const int lane = tid & 31;
    const int warp = tid >> 5;
    const int qb = (int)gridDim.x - 1 - (int)blockIdx.x;
    const int h  = blockIdx.y;
    const int kvh = h >> 2;
    const int q0 = qb * 128;
    const int NB = 2 * qb + 2;

    // ---- Stage Q through smem, build register fragments (single fp16)
    uint32_t qf[8][4];
    {
        for (int t = 0; t < 8; t++) {
            int idx = tid + t * 256;
            int r = idx >> 4, u = idx & 15;
            const __half* gp = Qf + (size_t)(q0 + r) * QDIM + h * HD + u * 8;
            asm volatile("cp.async.cg.shared.global [%0], [%1], 16;"
                         :: "r"(sb + swz256(r, u)), "l"(gp) : "memory");
        }
        asm volatile("cp.async.commit_group;" ::: "memory");
        asm volatile("cp.async.wait_group 0;" ::: "memory");
        __syncthreads();
        int r = warp * 16 + (lane & 15);
#pragma unroll
        for (int ks = 0; ks < 8; ks++)
            ldsm4(qf[ks], sb + swz256(r, 2 * ks + (lane >> 4)));
        __syncthreads();
    }

    float o[16][4];
#pragma unroll
    for (int i = 0; i < 16; i++)
#pragma unroll
        for (int q = 0; q < 4; q++) o[i][q] = 0.0f;
    float m0 = -1e30f, m1 = -1e30f, l0 = 0.0f, l1 = 0.0f;

    const int row0 = q0 + warp * 16 + (lane >> 2);
    const int row1 = row0 + 8;
    const int row_top = q0 + warp * 16 + 15;

    // ---- prologue: stages 0 and 1
    attn_load_kv(sb, Kf, Vf, 0, kvh, tid);
    asm volatile("cp.async.commit_group;" ::: "memory");
    if (NB > 1) {
        attn_load_kv(sb + ASTAGE_B, Kf, Vf, 64, kvh, tid);
        asm volatile("cp.async.commit_group;" ::: "memory");
    }

    int buf = 0;
    for (int kb = 0; kb < NB; kb++) {
        if (kb + 1 < NB)
            asm volatile("cp.async.wait_group 1;" ::: "memory");
        else
            asm volatile("cp.async.wait_group 0;" ::: "memory");
        __syncthreads();

        if (kb + 2 < NB) {
            int nb = buf + 2; if (nb >= 3) nb -= 3;
            attn_load_kv(sb + nb * ASTAGE_B, Kf, Vf, (kb + 2) * 64, kvh, tid);
            asm volatile("cp.async.commit_group;" ::: "memory");
        }

        const uint32_t bK = sb + buf * ASTAGE_B;
        const int k0 = kb * 64;

        if (k0 <= row_top) {   // skip fully-masked blocks (exact)

        // ---- S = Q K^T (single pass)
        float s[8][4];
#pragma unroll
        for (int nt = 0; nt < 8; nt++)
#pragma unroll
            for (int q = 0; q < 4; q++) s[nt][q] = 0.0f;

#pragma unroll
        for (int ks = 0; ks < 8; ks++) {
#pragma unroll
            for (int g = 0; g < 4; g++) {
                uint32_t kf4[4];
                int rr = g * 16 + ((lane >> 3) & 1) * 8 + (lane & 7);
                uint32_t off = swz256(rr, 2 * ks + (lane >> 4));
                ldsm4(kf4, bK + off);
#pragma unroll
                for (int sel = 0; sel < 2; sel++) {
                    int nt = g * 2 + sel;
                    mma16816h(s[nt], qf[ks], kf4[sel], kf4[sel + 2]);
                }
            }
        }

        // ---- scale + causal mask
        const bool domask = (k0 + 63) > row0;
#pragma unroll
        for (int nt = 0; nt < 8; nt++) {
            int c0 = k0 + nt * 8 + (lane & 3) * 2;
#pragma unroll
            for (int q = 0; q < 4; q++) s[nt][q] *= RSCALE;
            if (domask) {
                if (c0     > row0) s[nt][0] = -1e30f;
                if (c0 + 1 > row0) s[nt][1] = -1e30f;
                if (c0     > row1) s[nt][2] = -1e30f;
                if (c0 + 1 > row1) s[nt][3] = -1e30f;
            }
        }

        // ---- online softmax
        float mx0 = -1e30f, mx1 = -1e30f;
#pragma unroll
        for (int nt = 0; nt < 8; nt++) {
            mx0 = fmaxf(mx0, fmaxf(s[nt][0], s[nt][1]));
            mx1 = fmaxf(mx1, fmaxf(s[nt][2], s[nt][3]));
        }
        mx0 = fmaxf(mx0, __shfl_xor_sync(0xffffffffu, mx0, 1));
        mx0 = fmaxf(mx0, __shfl_xor_sync(0xffffffffu, mx0, 2));
        mx1 = fmaxf(mx1, __shfl_xor_sync(0xffffffffu, mx1, 1));
        mx1 = fmaxf(mx1, __shfl_xor_sync(0xffffffffu, mx1, 2));

        float mn0 = fmaxf(m0, mx0), mn1 = fmaxf(m1, mx1);
        float a0 = __expf(m0 - mn0), a1 = __expf(m1 - mn1);
        m0 = mn0; m1 = mn1;

        float sum0 = 0.0f, sum1 = 0.0f;
#pragma unroll
        for (int nt = 0; nt < 8; nt++) {
            s[nt][0] = __expf(s[nt][0] - mn0);
            s[nt][1] = __expf(s[nt][1] - mn0);
            s[nt][2] = __expf(s[nt][2] - mn1);
            s[nt][3] = __expf(s[nt][3] - mn1);
            sum0 += s[nt][0] + s[nt][1];
            sum1 += s[nt][2] + s[nt][3];
        }
        sum0 += __shfl_xor_sync(0xffffffffu, sum0, 1);
        sum0 += __shfl_xor_sync(0xffffffffu, sum0, 2);
        sum1 += __shfl_xor_sync(0xffffffffu, sum1, 1);
        sum1 += __shfl_xor_sync(0xffffffffu, sum1, 2);
        l0 = l0 * a0 + sum0;
        l1 = l1 * a1 + sum1;

#pragma unroll
        for (int nt = 0; nt < 16; nt++) {
            o[nt][0] *= a0; o[nt][1] *= a0;
            o[nt][2] *= a1; o[nt][3] *= a1;
        }

        // ---- O += P V (single pass)
#pragma unroll
        for (int kt = 0; kt < 4; kt++) {
            uint32_t pa[4];
            pa[0] = packh2(s[2*kt][0],   s[2*kt][1]);
            pa[1] = packh2(s[2*kt][2],   s[2*kt][3]);
            pa[2] = packh2(s[2*kt+1][0], s[2*kt+1][1]);
            pa[3] = packh2(s[2*kt+1][2], s[2*kt+1][3]);
            const int j = lane >> 3, ll = lane & 7;
            const int rr = kt * 16 + (j & 1) * 8 + ll;
#pragma unroll
            for (int gn = 0; gn < 8; gn++) {
                uint32_t vf4[4];
                uint32_t off = swz256(rr, gn * 2 + (j >> 1));
                ldsm4t(vf4, bK + KVTILE_B + off);
#pragma unroll
                for (int sel = 0; sel < 2; sel++) {
                    int nt = gn * 2 + sel;
                    mma16816h(o[nt], pa, vf4[sel * 2], vf4[sel * 2 + 1]);
                }
            }
        }

        }  // end fully-masked skip

        if (++buf == 3) buf = 0;
    }

    // ---- finalize: write AO as fp16 single
    const float i0 = 1.0f / l0, i1 = 1.0f / l1;
#pragma unroll
    for (int nt = 0; nt < 16; nt++) {
        int col = h * HD + nt * 8 + (lane & 3) * 2;
        *(__half2*)(Of + (size_t)row0 * QDIM + col) =
            __floats2half2_rn(o[nt][0] * i0, o[nt][1] * i0);
        *(__half2*)(Of + (size_t)row1 * QDIM + col) =
            __floats2half2_rn(o[nt][2] * i1, o[nt][3] * i1);
    }
}

// ---------------------------------------------------------------------------
extern "C" void kernel_launch(void* const* d_in, const int* in_sizes, int n_in,
                              void* d_out, int out_size)
{
    const float* hidden = (const float*)d_in[0];
    const float* cosb   = (const float*)d_in[1];
    const float* sinb   = (const float*)d_in[2];
    const float* Wq     = (const float*)d_in[3];
    const float* Wk     = (const float*)d_in[4];
    const float* Wv     = (const float*)d_in[5];
    const float* Wo     = (const float*)d_in[6];
    const float* qw     = (const float*)d_in[7];
    const float* kw     = (const float*)d_in[8];
    float* out = (float*)d_out;

    float *Qp, *Kp;
    cudaGetSymbolAddress((void**)&Qp,  g_Q);
    cudaGetSymbolAddress((void**)&Kp,  g_K);

    __half *Xf, *Wqf, *Wkf, *Wvf, *Wof, *AOf;
    __half *Qf2, *Kf2, *Vf2;
    cudaGetSymbolAddress((void**)&Xf,  g_Xf);
    cudaGetSymbolAddress((void**)&Wqf, g_Wqf);
    cudaGetSymbolAddress((void**)&Wkf, g_Wkf);
    cudaGetSymbolAddress((void**)&Wvf, g_Wvf);
    cudaGetSymbolAddress((void**)&Wof, g_Wof);
    cudaGetSymbolAddress((void**)&AOf, g_AOf);
    cudaGetSymbolAddress((void**)&Qf2, g_Qf2);
    cudaGetSymbolAddress((void**)&Kf2, g_Kf2);
    cudaGetSymbolAddress((void**)&Vf2, g_Vf2);

    cudaFuncSetAttribute(gemm_q_cvtwo,
                         cudaFuncAttributeMaxDynamicSharedMemorySize, GSM_TOTAL);
    cudaFuncSetAttribute(gemm_o,
                         cudaFuncAttributeMaxDynamicSharedMemorySize, GSM_TOTAL);
    cudaFuncSetAttribute(gemm_kv,
                         cudaFuncAttributeMaxDynamicSharedMemorySize, GSM_TOTAL);
    cudaFuncSetAttribute(attn_mma,
                         cudaFuncAttributeMaxDynamicSharedMemorySize, ASM_TOTAL);

    // L0: conversions (all single fp16). Wo folded into L1.
    cvt_all<<<CVT_BLOCKS, 256>>>(hidden, Xf, Wq, Wqf, Wk, Wkf, Wv, Wvf);

    // L1: Q projection + Wo conversion
    gemm_q_cvtwo<<<dim3(QDIM / 128 + 16, SEQ / 128), GTHREADS, GSM_TOTAL>>>(
        Xf, Wqf, Qp, Wo, Wof);

    // L2: fused K+V projection
    gemm_kv<<<dim3(2 * KVDIM / 128, SEQ / 128), GTHREADS, GSM_TOTAL>>>(
        Xf, Wkf, Wvf, Kp, Vf2);

    // L3: RMSNorm + RoPE (Q and K -> single fp16)
    rms_both<<<RMS_BLOCKS, 256>>>(Qp, Kp, qw, kw, cosb, sinb, Qf2, Kf2);

    // L4: flash attention -> fp16 AO
    attn_mma<<<dim3(SEQ / 128, NH), 256, ASM_TOTAL>>>(Qf2, Kf2, Vf2, AOf);

    // L5: output projection
    gemm_o<<<dim3(HID / 128, SEQ / 128), GTHREADS, GSM_TOTAL>>>(
        AOf, Wof, out);
}

// round 17
// speedup vs baseline: 2.9368x; 1.0075x over previous
#include <cuda_runtime.h>
#include <cuda_fp16.h>
#include <stdint.h>
#include <math.h>

// Problem constants (B=1)
#define SEQ   2048
#define HID   4096
#define NH    32
#define NKV   8
#define HD    128
#define QDIM  (NH * HD)   // 4096
#define KVDIM (NKV * HD)  // 1024
#define RSCALE 0.08838834764831845f  // 128^-0.5
#define REPS   1e-6f

// ---------------------------------------------------------------------------
// Scratch (__device__ globals: allocation-free rule)
// ---------------------------------------------------------------------------
__device__ float g_Q[SEQ * QDIM];
__device__ float g_K[SEQ * KVDIM];

__device__ __half g_Xf[SEQ * HID];
__device__ __half g_Wqf[QDIM * HID];
__device__ __half g_Wkf[KVDIM * HID];
__device__ __half g_Wvf[KVDIM * HID];
__device__ __half g_Wof[HID * QDIM];
__device__ __half g_AOf[SEQ * QDIM];

__device__ __half g_Qf2[SEQ * QDIM];
__device__ __half g_Kf2[SEQ * KVDIM];
__device__ __half g_Vf2[SEQ * KVDIM];

// ---------------------------------------------------------------------------
// PTX helpers (base sm_100-safe)
// ---------------------------------------------------------------------------
__device__ __forceinline__ uint32_t smem_u32(const void* p) {
    uint32_t a;
    asm("{ .reg .u64 t; cvta.to.shared.u64 t, %1; cvt.u32.u64 %0, t; }"
        : "=r"(a) : "l"(p));
    return a;
}

__device__ __forceinline__ void ldsm4(uint32_t* r, uint32_t addr) {
    asm volatile("ldmatrix.sync.aligned.m8n8.x4.shared.b16 {%0,%1,%2,%3}, [%4];"
                 : "=r"(r[0]), "=r"(r[1]), "=r"(r[2]), "=r"(r[3]) : "r"(addr));
}

__device__ __forceinline__ void ldsm4t(uint32_t* r, uint32_t addr) {
    asm volatile("ldmatrix.sync.aligned.m8n8.x4.trans.shared.b16 {%0,%1,%2,%3}, [%4];"
                 : "=r"(r[0]), "=r"(r[1]), "=r"(r[2]), "=r"(r[3]) : "r"(addr));
}

// fp16 inputs, fp32 accumulate
__device__ __forceinline__ void mma16816h(float* c, const uint32_t* a,
                                          uint32_t b0, uint32_t b1) {
    asm volatile(
        "mma.sync.aligned.m16n8k16.row.col.f32.f16.f16.f32 "
        "{%0,%1,%2,%3}, {%4,%5,%6,%7}, {%8,%9}, {%0,%1,%2,%3};"
        : "+f"(c[0]), "+f"(c[1]), "+f"(c[2]), "+f"(c[3])
        : "r"(a[0]), "r"(a[1]), "r"(a[2]), "r"(a[3]), "r"(b0), "r"(b1));
}

__device__ __forceinline__ uint32_t packh2(float lo, float hi) {
    __half2 t = __floats2half2_rn(lo, hi);
    return *(uint32_t*)&t;
}

// ---------------------------------------------------------------------------
// Fused conversions: X, Wq, Wk, Wv -> fp16 single.
//   X: [0, 8192)  Wq: [8192, 24576)  Wk: [24576, 28672)  Wv: [28672, 32768)
// ---------------------------------------------------------------------------
#define CVT_BLOCKS 32768

__global__ __launch_bounds__(256) void cvt_all(
    const float* __restrict__ x,  __half* __restrict__ xf,
    const float* __restrict__ wq, __half* __restrict__ wqf,
    const float* __restrict__ wk, __half* __restrict__ wkf,
    const float* __restrict__ wv, __half* __restrict__ wvf)
{
    const int b = blockIdx.x;
    const float* src;
    __half* dst;
    int base;
    if (b < 8192)       { src = x;  dst = xf;  base = 0; }
    else if (b < 24576) { src = wq; dst = wqf; base = 8192; }
    else if (b < 28672) { src = wk; dst = wkf; base = 24576; }
    else                { src = wv; dst = wvf; base = 28672; }
    const int i = ((b - base) * 256 + threadIdx.x) * 4;
    float4 v = *(const float4*)(src + i);
    *(__half2*)(dst + i)     = __floats2half2_rn(v.x, v.y);
    *(__half2*)(dst + i + 2) = __floats2half2_rn(v.z, v.w);
}

// ---------------------------------------------------------------------------
// mma.sync fp16 single-single GEMM core: C = Af[M,K] * Bf[N,K]^T, 1 pass.
// 512 threads, 128x128 CTA tile, BK=64, 3-stage cp.async pipeline.
// ---------------------------------------------------------------------------
#define GTHREADS 512
#define TILE_B   16384                 // 128 rows x 128B (64 fp16 cols)
#define GSTAGE_B (2 * TILE_B)          // Af, Bf
#define GSM_TOTAL (3 * GSTAGE_B)       // 98304

__device__ __forceinline__ void load_tile64(
    uint32_t sdst, const __half* __restrict__ g,
    int row0, int kc, int K, int tid)
{
#pragma unroll
    for (int s = 0; s < 2; s++) {
        int idx = tid + s * GTHREADS;
        int r = idx >> 3;
        int u = idx & 7;
        uint32_t sw = (uint32_t)(r * 128 + ((u ^ (r & 7)) << 4));
        const __half* gp = g + (size_t)(row0 + r) * K + kc * 64 + u * 8;
        asm volatile("cp.async.cg.shared.global [%0], [%1], 16;"
                     :: "r"(sdst + sw), "l"(gp) : "memory");
    }
}

__device__ __forceinline__ void gemm_core(
    const __half* __restrict__ Af, const __half* __restrict__ Bf,
    float* __restrict__ C, __half* __restrict__ Ch,
    int N, int K, int bm, int bn, char* smem)
{
    const uint32_t sb = smem_u32(smem);
    const int tid  = threadIdx.x;
    const int lane = tid & 31;
    const int warp = tid >> 5;
    const int wm = warp >> 2;
    const int wn = warp & 3;
    const int NC = K >> 6;

    float acc[2][4][4];
#pragma unroll
    for (int i = 0; i < 2; i++)
#pragma unroll
        for (int j = 0; j < 4; j++)
#pragma unroll
            for (int q = 0; q < 4; q++) acc[i][j][q] = 0.0f;

    // Prologue: stages 0 and 1
#pragma unroll
    for (int c = 0; c < 2; c++) {
        uint32_t b = sb + c * GSTAGE_B;
        load_tile64(b,          Af, bm, c, K, tid);
        load_tile64(b + TILE_B, Bf, bn, c, K, tid);
        asm volatile("cp.async.commit_group;" ::: "memory");
    }

    const int a_r  = wm * 32 + (lane & 15);
    const int a_ku = lane >> 4;
    const int b_r  = wn * 32 + ((lane >> 3) & 1) * 8 + (lane & 7);
    const int b_ku = lane >> 4;

    int buf = 0;
    for (int c = 0; c < NC; c++) {
        if (c + 1 < NC)
            asm volatile("cp.async.wait_group 1;" ::: "memory");
        else
            asm volatile("cp.async.wait_group 0;" ::: "memory");
        __syncthreads();

        if (c + 2 < NC) {
            int nb = buf + 2; if (nb >= 3) nb -= 3;
            uint32_t b2 = sb + nb * GSTAGE_B;
            load_tile64(b2,          Af, bm, c + 2, K, tid);
            load_tile64(b2 + TILE_B, Bf, bn, c + 2, K, tid);
            asm volatile("cp.async.commit_group;" ::: "memory");
        }

        const uint32_t b = sb + buf * GSTAGE_B;
        const uint32_t sAf = b;
        const uint32_t sBf = b + TILE_B;

#pragma unroll
        for (int ks = 0; ks < 4; ks++) {
            const int ku0 = ks * 2;
            uint32_t aF[2][4];
#pragma unroll
            for (int mt = 0; mt < 2; mt++) {
                int r = a_r + mt * 16;
                int ku = ku0 + a_ku;
                uint32_t off = (uint32_t)(r * 128 + ((ku ^ (r & 7)) << 4));
                ldsm4(aF[mt], sAf + off);
            }
            uint32_t bF[2][4];
#pragma unroll
            for (int ntp = 0; ntp < 2; ntp++) {
                int r = b_r + ntp * 16;
                int ku = ku0 + b_ku;
                uint32_t off = (uint32_t)(r * 128 + ((ku ^ (r & 7)) << 4));
                ldsm4(bF[ntp], sBf + off);
            }
#pragma unroll
            for (int mt = 0; mt < 2; mt++) {
#pragma unroll
                for (int nt = 0; nt < 4; nt++) {
                    const int ntp = nt >> 1;
                    const int sel = nt & 1;
                    mma16816h(acc[mt][nt], aF[mt], bF[ntp][sel], bF[ntp][sel + 2]);
                }
            }
        }
        if (++buf == 3) buf = 0;
    }

    // Epilogue: fp32 (C) or fp16-single (Ch)
#pragma unroll
    for (int mt = 0; mt < 2; mt++) {
        const int row = bm + wm * 32 + mt * 16 + (lane >> 2);
#pragma unroll
        for (int nt = 0; nt < 4; nt++) {
            const int col = bn + wn * 32 + nt * 8 + (lane & 3) * 2;
            if (C) {
                *(float2*)(C + (size_t)row * N + col) =
                    make_float2(acc[mt][nt][0], acc[mt][nt][1]);
                *(float2*)(C + (size_t)(row + 8) * N + col) =
                    make_float2(acc[mt][nt][2], acc[mt][nt][3]);
            } else {
                *(__half2*)(Ch + (size_t)row * N + col) =
                    __floats2half2_rn(acc[mt][nt][0], acc[mt][nt][1]);
                *(__half2*)(Ch + (size_t)(row + 8) * N + col) =
                    __floats2half2_rn(acc[mt][nt][2], acc[mt][nt][3]);
            }
        }
    }
}

// Fused Q + K + V projection + Wo conversion, one launch.
// bx [0,32): Q tiles. [32,40): K tiles. [40,48): V tiles. [48,64): Wo cvt.
__global__ __launch_bounds__(GTHREADS)
void gemm_qkv(const __half* __restrict__ Af,
              const __half* __restrict__ Bqf, const __half* __restrict__ Bkf,
              const __half* __restrict__ Bvf,
              float* __restrict__ Cq, float* __restrict__ Ck,
              __half* __restrict__ Cvf,
              const float* __restrict__ wo, __half* __restrict__ wof)
{
    extern __shared__ __align__(1024) char smem[];
    const int bx = blockIdx.x;
    if (bx < 32) {
        gemm_core(Af, Bqf, Cq, nullptr, QDIM, HID,
                  blockIdx.y * 128, bx * 128, smem);
    } else if (bx < 40) {
        gemm_core(Af, Bkf, Ck, nullptr, KVDIM, HID,
                  blockIdx.y * 128, (bx - 32) * 128, smem);
    } else if (bx < 48) {
        gemm_core(Af, Bvf, nullptr, Cvf, KVDIM, HID,
                  blockIdx.y * 128, (bx - 40) * 128, smem);
    } else {
        const int sid = (bx - 48) * (int)gridDim.y + blockIdx.y;  // 0..255
        const size_t n_per = ((size_t)HID * QDIM) / 256;          // 65536
        const size_t base = (size_t)sid * n_per;
        for (size_t i = base + threadIdx.x * 4; i < base + n_per;
             i += (size_t)GTHREADS * 4) {
            float4 v = *(const float4*)(wo + i);
            *(__half2*)(wof + i)     = __floats2half2_rn(v.x, v.y);
            *(__half2*)(wof + i + 2) = __floats2half2_rn(v.z, v.w);
        }
    }
}

// O projection
__global__ __launch_bounds__(GTHREADS)
void gemm_o(const __half* __restrict__ Af, const __half* __restrict__ Bf,
            float* __restrict__ C)
{
    extern __shared__ __align__(1024) char smem[];
    gemm_core(Af, Bf, C, nullptr, HID, QDIM,
              blockIdx.y * 128, blockIdx.x * 128, smem);
}

// ---------------------------------------------------------------------------
// Fused RMSNorm + RoPE. Q and K -> fp16 single.
// ---------------------------------------------------------------------------
#define RMS_BLOCKS (8192 + 2048)

__global__ __launch_bounds__(256) void rms_both(
    const float* __restrict__ Qf, const float* __restrict__ Kf,
    const float* __restrict__ qw, const float* __restrict__ kw,
    const float* __restrict__ cosb, const float* __restrict__ sinb,
    __half* __restrict__ qf, __half* __restrict__ kf)
{
    const int b = blockIdx.x;
    const float* X;
    const float* w;
    __half* dst;
    int nheads, row;
    if (b < 8192) { X = Qf; w = qw; dst = qf; nheads = NH;  row = b * 8; }
    else          { X = Kf; w = kw; dst = kf; nheads = NKV; row = (b - 8192) * 8; }
    row += threadIdx.x >> 5;
    const int lane = threadIdx.x & 31;
    const int s = row / nheads;

    const float* x = X + (size_t)row * HD;
    float4 v = *(const float4*)(x + lane * 4);

    float ss = v.x * v.x + v.y * v.y + v.z * v.z + v.w * v.w;
#pragma unroll
    for (int o = 16; o > 0; o >>= 1) ss += __shfl_xor_sync(0xffffffffu, ss, o);
    const float inv = rsqrtf(ss * (1.0f / 128.0f) + REPS);

    float4 wv = *(const float4*)(w + lane * 4);
    float x0 = v.x * inv * wv.x;
    float x1 = v.y * inv * wv.y;
    float x2 = v.z * inv * wv.z;
    float x3 = v.w * inv * wv.w;

    float p0 = __shfl_xor_sync(0xffffffffu, x0, 16);
    float p1 = __shfl_xor_sync(0xffffffffu, x1, 16);
    float p2 = __shfl_xor_sync(0xffffffffu, x2, 16);
    float p3 = __shfl_xor_sync(0xffffffffu, x3, 16);
    const float sgn = (lane < 16) ? -1.0f : 1.0f;

    const float* cp = cosb + (size_t)s * HD + lane * 4;
    const float* sp = sinb + (size_t)s * HD + lane * 4;
    float4 c = *(const float4*)cp;
    float4 sn = *(const float4*)sp;

    float o0 = x0 * c.x + sgn * p0 * sn.x;
    float o1 = x1 * c.y + sgn * p1 * sn.y;
    float o2 = x2 * c.z + sgn * p2 * sn.z;
    float o3 = x3 * c.w + sgn * p3 * sn.w;

    size_t base = (size_t)row * HD + lane * 4;
    *(__half2*)(dst + base)     = __floats2half2_rn(o0, o1);
    *(__half2*)(dst + base + 2) = __floats2half2_rn(o2, o3);
}

// ---------------------------------------------------------------------------
// Tensor-core flash attention (fp16 single everywhere), causal, GQA,
// 3-stage pipeline, warp-level skip of fully-masked blocks.
// Writes AO as fp16 single.
// ---------------------------------------------------------------------------
#define KVTILE_B 16384                    // 64 rows x 256B
#define ASTAGE_B (2 * KVTILE_B)           // Kf, Vf
#define ASM_TOTAL (3 * ASTAGE_B)          // 98304

__device__ __forceinline__ uint32_t swz256(int r, int u) {
    return (uint32_t)(r * 256 + ((u ^ (r & 7)) << 4));
}

__device__ __forceinline__ void attn_load_kv(
    uint32_t base, const __half* __restrict__ Kf,
    const __half* __restrict__ Vf, int k0, int kvh, int tid)
{
#pragma unroll
    for (int t = 0; t < 4; t++) {
        int idx = tid + t * 256;
        int r = idx >> 4, u = idx & 15;
        size_t go = (size_t)(k0 + r) * KVDIM + kvh * HD + u * 8;
        uint32_t sw = swz256(r, u);
        asm volatile("cp.async.cg.shared.global [%0], [%1], 16;"
                     :: "r"(base + sw), "l"(Kf + go) : "memory");
        asm volatile("cp.async.cg.shared.global [%0], [%1], 16;"
                     :: "r"(base + KVTILE_B + sw), "l"(Vf + go) : "memory");
    }
}

__global__ __launch_bounds__(256, 1)
void attn_mma(const __half* __restrict__ Qf, const __half* __restrict__ Kf,
              const __half* __restrict__ Vf, __half* __restrict__ Of)
{
    extern __shared__ __align__(1024) char smem[];
    const uint32_t sb = smem_u32(smem);
    const int tid  = threadIdx.x;
    const int lane = tid & 31;
    const int warp = tid >> 5;
    const int qb = (int)gridDim.x - 1 - (int)blockIdx.x;
    const int h  = blockIdx.y;
    const int kvh = h >> 2;
    const int q0 = qb * 128;
    const int NB = 2 * qb + 2;

    // ---- Stage Q through smem, build register fragments (single fp16)
    uint32_t qf[8][4];
    {
        for (int t = 0; t < 8; t++) {
            int idx = tid + t * 256;
            int r = idx >> 4, u = idx & 15;
            const __half* gp = Qf + (size_t)(q0 + r) * QDIM + h * HD + u * 8;
            asm volatile("cp.async.cg.shared.global [%0], [%1], 16;"
                         :: "r"(sb + swz256(r, u)), "l"(gp) : "memory");
        }
        asm volatile("cp.async.commit_group;" ::: "memory");
        asm volatile("cp.async.wait_group 0;" ::: "memory");
        __syncthreads();
        int r = warp * 16 + (lane & 15);
#pragma unroll
        for (int ks = 0; ks < 8; ks++)
            ldsm4(qf[ks], sb + swz256(r, 2 * ks + (lane >> 4)));
        __syncthreads();
    }

    float o[16][4];
#pragma unroll
    for (int i = 0; i < 16; i++)
#pragma unroll
        for (int q = 0; q < 4; q++) o[i][q] = 0.0f;
    float m0 = -1e30f, m1 = -1e30f, l0 = 0.0f, l1 = 0.0f;

    const int row0 = q0 + warp * 16 + (lane >> 2);
    const int row1 = row0 + 8;
    const int row_top = q0 + warp * 16 + 15;

    // ---- prologue: stages 0 and 1
    attn_load_kv(sb, Kf, Vf, 0, kvh, tid);
    asm volatile("cp.async.commit_group;" ::: "memory");
    if (NB > 1) {
        attn_load_kv(sb + ASTAGE_B, Kf, Vf, 64, kvh, tid);
        asm volatile("cp.async.commit_group;" ::: "memory");
    }

    int buf = 0;
    for (int kb = 0; kb < NB; kb++) {
        if (kb + 1 < NB)
            asm volatile("cp.async.wait_group 1;" ::: "memory");
        else
            asm volatile("cp.async.wait_group 0;" ::: "memory");
        __syncthreads();

        if (kb + 2 < NB) {
            int nb = buf + 2; if (nb >= 3) nb -= 3;
            attn_load_kv(sb + nb * ASTAGE_B, Kf, Vf, (kb + 2) * 64, kvh, tid);
            asm volatile("cp.async.commit_group;" ::: "memory");
        }

        const uint32_t bK = sb + buf * ASTAGE_B;
        const int k0 = kb * 64;

        if (k0 <= row_top) {   // skip fully-masked blocks (exact)

        // ---- S = Q K^T (single pass)
        float s[8][4];
#pragma unroll
        for (int nt = 0; nt < 8; nt++)
#pragma unroll
            for (int q = 0; q < 4; q++) s[nt][q] = 0.0f;

#pragma unroll
        for (int ks = 0; ks < 8; ks++) {
#pragma unroll
            for (int g = 0; g < 4; g++) {
                uint32_t kf4[4];
                int rr = g * 16 + ((lane >> 3) & 1) * 8 + (lane & 7);
                uint32_t off = swz256(rr, 2 * ks + (lane >> 4));
                ldsm4(kf4, bK + off);
#pragma unroll
                for (int sel = 0; sel < 2; sel++) {
                    int nt = g * 2 + sel;
                    mma16816h(s[nt], qf[ks], kf4[sel], kf4[sel + 2]);
                }
            }
        }

        // ---- scale + causal mask
        const bool domask = (k0 + 63) > row0;
#pragma unroll
        for (int nt = 0; nt < 8; nt++) {
            int c0 = k0 + nt * 8 + (lane & 3) * 2;
#pragma unroll
            for (int q = 0; q < 4; q++) s[nt][q] *= RSCALE;
            if (domask) {
                if (c0     > row0) s[nt][0] = -1e30f;
                if (c0 + 1 > row0) s[nt][1] = -1e30f;
                if (c0     > row1) s[nt][2] = -1e30f;
                if (c0 + 1 > row1) s[nt][3] = -1e30f;
            }
        }

        // ---- online softmax
        float mx0 = -1e30f, mx1 = -1e30f;
#pragma unroll
        for (int nt = 0; nt < 8; nt++) {
            mx0 = fmaxf(mx0, fmaxf(s[nt][0], s[nt][1]));
            mx1 = fmaxf(mx1, fmaxf(s[nt][2], s[nt][3]));
        }
        mx0 = fmaxf(mx0, __shfl_xor_sync(0xffffffffu, mx0, 1));
        mx0 = fmaxf(mx0, __shfl_xor_sync(0xffffffffu, mx0, 2));
        mx1 = fmaxf(mx1, __shfl_xor_sync(0xffffffffu, mx1, 1));
        mx1 = fmaxf(mx1, __shfl_xor_sync(0xffffffffu, mx1, 2));

        float mn0 = fmaxf(m0, mx0), mn1 = fmaxf(m1, mx1);
        float a0 = __expf(m0 - mn0), a1 = __expf(m1 - mn1);
        m0 = mn0; m1 = mn1;

        float sum0 = 0.0f, sum1 = 0.0f;
#pragma unroll
        for (int nt = 0; nt < 8; nt++) {
            s[nt][0] = __expf(s[nt][0] - mn0);
            s[nt][1] = __expf(s[nt][1] - mn0);
            s[nt][2] = __expf(s[nt][2] - mn1);
            s[nt][3] = __expf(s[nt][3] - mn1);
            sum0 += s[nt][0] + s[nt][1];
            sum1 += s[nt][2] + s[nt][3];
        }
        sum0 += __shfl_xor_sync(0xffffffffu, sum0, 1);
        sum0 += __shfl_xor_sync(0xffffffffu, sum0, 2);
        sum1 += __shfl_xor_sync(0xffffffffu, sum1, 1);
        sum1 += __shfl_xor_sync(0xffffffffu, sum1, 2);
        l0 = l0 * a0 + sum0;
        l1 = l1 * a1 + sum1;

#pragma unroll
        for (int nt = 0; nt < 16; nt++) {
            o[nt][0] *= a0; o[nt][1] *= a0;
            o[nt][2] *= a1; o[nt][3] *= a1;
        }

        // ---- O += P V (single pass)
#pragma unroll
        for (int kt = 0; kt < 4; kt++) {
            uint32_t pa[4];
            pa[0] = packh2(s[2*kt][0],   s[2*kt][1]);
            pa[1] = packh2(s[2*kt][2],   s[2*kt][3]);
            pa[2] = packh2(s[2*kt+1][0], s[2*kt+1][1]);
            pa[3] = packh2(s[2*kt+1][2], s[2*kt+1][3]);
            const int j = lane >> 3, ll = lane & 7;
            const int rr = kt * 16 + (j & 1) * 8 + ll;
#pragma unroll
            for (int gn = 0; gn < 8; gn++) {
                uint32_t vf4[4];
                uint32_t off = swz256(rr, gn * 2 + (j >> 1));
                ldsm4t(vf4, bK + KVTILE_B + off);
#pragma unroll
                for (int sel = 0; sel < 2; sel++) {
                    int nt = gn * 2 + sel;
                    mma16816h(o[nt], pa, vf4[sel * 2], vf4[sel * 2 + 1]);
                }
            }
        }

        }  // end fully-masked skip

        if (++buf == 3) buf = 0;
    }

    // ---- finalize: write AO as fp16 single
    const float i0 = 1.0f / l0, i1 = 1.0f / l1;
#pragma unroll
    for (int nt = 0; nt < 16; nt++) {
        int col = h * HD + nt * 8 + (lane & 3) * 2;
        *(__half2*)(Of + (size_t)row0 * QDIM + col) =
            __floats2half2_rn(o[nt][0] * i0, o[nt][1] * i0);
        *(__half2*)(Of + (size_t)row1 * QDIM + col) =
            __floats2half2_rn(o[nt][2] * i1, o[nt][3] * i1);
    }
}

// ---------------------------------------------------------------------------
extern "C" void kernel_launch(void* const* d_in, const int* in_sizes, int n_in,
                              void* d_out, int out_size)
{
    const float* hidden = (const float*)d_in[0];
    const float* cosb   = (const float*)d_in[1];
    const float* sinb   = (const float*)d_in[2];
    const float* Wq     = (const float*)d_in[3];
    const float* Wk     = (const float*)d_in[4];
    const float* Wv     = (const float*)d_in[5];
    const float* Wo     = (const float*)d_in[6];
    const float* qw     = (const float*)d_in[7];
    const float* kw     = (const float*)d_in[8];
    float* out = (float*)d_out;

    float *Qp, *Kp;
    cudaGetSymbolAddress((void**)&Qp,  g_Q);
    cudaGetSymbolAddress((void**)&Kp,  g_K);

    __half *Xf, *Wqf, *Wkf, *Wvf, *Wof, *AOf;
    __half *Qf2, *Kf2, *Vf2;
    cudaGetSymbolAddress((void**)&Xf,  g_Xf);
    cudaGetSymbolAddress((void**)&Wqf, g_Wqf);
    cudaGetSymbolAddress((void**)&Wkf, g_Wkf);
    cudaGetSymbolAddress((void**)&Wvf, g_Wvf);
    cudaGetSymbolAddress((void**)&Wof, g_Wof);
    cudaGetSymbolAddress((void**)&AOf, g_AOf);
    cudaGetSymbolAddress((void**)&Qf2, g_Qf2);
    cudaGetSymbolAddress((void**)&Kf2, g_Kf2);
    cudaGetSymbolAddress((void**)&Vf2, g_Vf2);

    cudaFuncSetAttribute(gemm_qkv,
                         cudaFuncAttributeMaxDynamicSharedMemorySize, GSM_TOTAL);
    cudaFuncSetAttribute(gemm_o,
                         cudaFuncAttributeMaxDynamicSharedMemorySize, GSM_TOTAL);
    cudaFuncSetAttribute(attn_mma,
                         cudaFuncAttributeMaxDynamicSharedMemorySize, ASM_TOTAL);

    // L0: conversions (all single fp16). Wo folded into L1.
    cvt_all<<<CVT_BLOCKS, 256>>>(hidden, Xf, Wq, Wqf, Wk, Wkf, Wv, Wvf);

    // L1: Q + K + V projections + Wo conversion (one launch)
    gemm_qkv<<<dim3(64, SEQ / 128), GTHREADS, GSM_TOTAL>>>(
        Xf, Wqf, Wkf, Wvf, Qp, Kp, Vf2, Wo, Wof);

    // L2: RMSNorm + RoPE (Q and K -> single fp16)
    rms_both<<<RMS_BLOCKS, 256>>>(Qp, Kp, qw, kw, cosb, sinb, Qf2, Kf2);

    // L3: flash attention -> fp16 AO
    attn_mma<<<dim3(SEQ / 128, NH), 256, ASM_TOTAL>>>(Qf2, Kf2, Vf2, AOf);

    // L4: output projection
    gemm_o<<<dim3(HID / 128, SEQ / 128), GTHREADS, GSM_TOTAL>>>(
        AOf, Wof, out);
}